// round 1
// baseline (speedup 1.0000x reference)
#include <cuda_runtime.h>
#include <cuda_bf16.h>

// Problem constants (shapes are fixed by the dataset)
#define NN 50000
#define EE 800000
#define DD 128

// Scratch (static device globals: allocation-free per harness rules)
__device__ float g_aggr[(size_t)NN * DD];        // 25.6 MB
__device__ float g_h[(size_t)NN * 2 * DD];       // 51.2 MB
__device__ float g_y0[(size_t)NN * DD];          // 25.6 MB

// ---------------------------------------------------------------------------
// Zero kernel (float4)
// ---------------------------------------------------------------------------
__global__ void zero_kernel(float4* __restrict__ p, long n4) {
    long i = (long)blockIdx.x * blockDim.x + threadIdx.x;
    if (i < n4) p[i] = make_float4(0.f, 0.f, 0.f, 0.f);
}

// ---------------------------------------------------------------------------
// Scatter: aggr[dst] += x[src] + ee1[attr0] + ee2[attr1]
// One warp per edge, each lane handles 4 contiguous floats (float4).
// Uses vectorized reduction (red.global.add.v4.f32, sm_90+).
// ---------------------------------------------------------------------------
__global__ void __launch_bounds__(256)
scatter_kernel(const float* __restrict__ x,
               const int* __restrict__ ei,    // [2, E]
               const int* __restrict__ ea,    // [E, 2]
               const float* __restrict__ ee1, // [6, D]
               const float* __restrict__ ee2, // [3, D]
               float* __restrict__ aggr,
               int E) {
    long idx = (long)blockIdx.x * blockDim.x + threadIdx.x;
    int e = (int)(idx >> 5);
    if (e >= E) return;
    int lane = (int)(idx & 31);
    int d = lane * 4;

    int src = ei[e];
    int dst = ei[E + e];
    int a0 = ea[2 * e];
    int a1 = ea[2 * e + 1];

    float4 xv = *(const float4*)(x + (long)src * DD + d);
    float4 v1 = *(const float4*)(ee1 + a0 * DD + d);
    float4 v2 = *(const float4*)(ee2 + a1 * DD + d);

    float4 v;
    v.x = xv.x + v1.x + v2.x;
    v.y = xv.y + v1.y + v2.y;
    v.z = xv.z + v1.z + v2.z;
    v.w = xv.w + v1.w + v2.w;

    float* p = aggr + (long)dst * DD + d;
    asm volatile("red.global.add.v4.f32 [%0], {%1, %2, %3, %4};"
                 :: "l"(p), "f"(v.x), "f"(v.y), "f"(v.z), "f"(v.w)
                 : "memory");
}

// ---------------------------------------------------------------------------
// SGEMM with bias + optional relu: C[M,N] = act(A[M,K] @ W[K,N] + b[N])
// Block tile 128x128, K-tile 16, thread tile 8x8, 256 threads.
// M may be ragged; K and N must be multiples of 16/128 (true here: 128/256).
// ---------------------------------------------------------------------------
template <bool RELU>
__global__ void __launch_bounds__(256)
gemm_bias(const float* __restrict__ A, const float* __restrict__ W,
          const float* __restrict__ bias, float* __restrict__ C,
          int M, int N, int K) {
    constexpr int BM = 128, BN = 128, BK = 16, TM = 8, TN = 8;
    __shared__ float As[BK][BM];   // transposed A tile
    __shared__ float Ws[BK][BN];

    const int tid = threadIdx.x;
    const int brow = blockIdx.y * BM;
    const int bcol = blockIdx.x * BN;
    const int trow = (tid / 16) * TM;
    const int tcol = (tid % 16) * TN;

    // A load mapping: each thread loads 2x float4 (rows tid/4 and tid/4+64)
    const int a_r = tid >> 2;
    const int a_c = (tid & 3) * 4;
    // W load mapping: each thread loads 2x float4 (rows tid/32 and tid/32+8)
    const int w_r = tid >> 5;
    const int w_c = (tid & 31) * 4;

    float acc[TM][TN] = {};

    for (int k0 = 0; k0 < K; k0 += BK) {
#pragma unroll
        for (int h = 0; h < 2; h++) {
            int r = a_r + h * 64;
            int grow = brow + r;
            float4 v = make_float4(0.f, 0.f, 0.f, 0.f);
            if (grow < M) v = *(const float4*)(A + (long)grow * K + k0 + a_c);
            As[a_c + 0][r] = v.x;
            As[a_c + 1][r] = v.y;
            As[a_c + 2][r] = v.z;
            As[a_c + 3][r] = v.w;
        }
#pragma unroll
        for (int h = 0; h < 2; h++) {
            int r = w_r + h * 8;
            *(float4*)&Ws[r][w_c] =
                *(const float4*)(W + (long)(k0 + r) * N + bcol + w_c);
        }
        __syncthreads();

#pragma unroll
        for (int kk = 0; kk < BK; kk++) {
            float ra[TM], rw[TN];
#pragma unroll
            for (int i = 0; i < TM; i++) ra[i] = As[kk][trow + i];
#pragma unroll
            for (int j = 0; j < TN; j++) rw[j] = Ws[kk][tcol + j];
#pragma unroll
            for (int i = 0; i < TM; i++)
#pragma unroll
                for (int j = 0; j < TN; j++)
                    acc[i][j] = fmaf(ra[i], rw[j], acc[i][j]);
        }
        __syncthreads();
    }

    // Epilogue
#pragma unroll
    for (int i = 0; i < TM; i++) {
        int grow = brow + trow + i;
        if (grow >= M) break;
#pragma unroll
        for (int j = 0; j < TN; j += 4) {
            int gcol = bcol + tcol + j;
            float4 o;
            o.x = acc[i][j + 0] + bias[gcol + 0];
            o.y = acc[i][j + 1] + bias[gcol + 1];
            o.z = acc[i][j + 2] + bias[gcol + 2];
            o.w = acc[i][j + 3] + bias[gcol + 3];
            if (RELU) {
                o.x = fmaxf(o.x, 0.f);
                o.y = fmaxf(o.y, 0.f);
                o.z = fmaxf(o.z, 0.f);
                o.w = fmaxf(o.w, 0.f);
            }
            *(float4*)(C + (long)grow * N + gcol) = o;
        }
    }
}

// ---------------------------------------------------------------------------
// Launch
// ---------------------------------------------------------------------------
extern "C" void kernel_launch(void* const* d_in, const int* in_sizes, int n_in,
                              void* d_out, int out_size) {
    const float* x    = (const float*)d_in[0];
    const int*   ei   = (const int*)d_in[1];
    const int*   ea   = (const int*)d_in[2];
    const float* ee1_0 = (const float*)d_in[3];
    const float* ee2_0 = (const float*)d_in[4];
    const float* W1_0  = (const float*)d_in[5];
    const float* b1_0  = (const float*)d_in[6];
    const float* W2_0  = (const float*)d_in[7];
    const float* b2_0  = (const float*)d_in[8];
    const float* ee1_1 = (const float*)d_in[9];
    const float* ee2_1 = (const float*)d_in[10];
    const float* W1_1  = (const float*)d_in[11];
    const float* b1_1  = (const float*)d_in[12];
    const float* W2_1  = (const float*)d_in[13];
    const float* b2_1  = (const float*)d_in[14];
    float* out = (float*)d_out;

    const int N = in_sizes[0] / DD;   // 50000
    const int E = in_sizes[1] / 2;    // 800000

    float *aggr, *h, *y0;
    cudaGetSymbolAddress((void**)&aggr, g_aggr);
    cudaGetSymbolAddress((void**)&h, g_h);
    cudaGetSymbolAddress((void**)&y0, g_y0);

    const long n4_aggr = (long)N * DD / 4;
    const int ZB = 256;
    dim3 zgrid((unsigned)((n4_aggr + ZB - 1) / ZB));

    const long sc_threads = (long)E * 32;
    dim3 sgrid((unsigned)((sc_threads + 255) / 256));

    dim3 g1grid(2, (N + 127) / 128);   // N_out = 256
    dim3 g2grid(1, (N + 127) / 128);   // N_out = 128

    // ---- layer 0 ----
    zero_kernel<<<zgrid, ZB>>>((float4*)aggr, n4_aggr);
    scatter_kernel<<<sgrid, 256>>>(x, ei, ea, ee1_0, ee2_0, aggr, E);
    gemm_bias<true><<<g1grid, 256>>>(aggr, W1_0, b1_0, h, N, 2 * DD, DD);
    gemm_bias<true><<<g2grid, 256>>>(h, W2_0, b2_0, y0, N, DD, 2 * DD); // inter-layer relu

    // ---- layer 1 ----
    zero_kernel<<<zgrid, ZB>>>((float4*)aggr, n4_aggr);
    scatter_kernel<<<sgrid, 256>>>(y0, ei, ea, ee1_1, ee2_1, aggr, E);
    gemm_bias<true><<<g1grid, 256>>>(aggr, W1_1, b1_1, h, N, 2 * DD, DD);
    gemm_bias<false><<<g2grid, 256>>>(h, W2_1, b2_1, out, N, DD, 2 * DD);
}

// round 3
// speedup vs baseline: 1.4119x; 1.4119x over previous
#include <cuda_runtime.h>
#include <cuda_bf16.h>
#include <cstdint>

#define NN 50000
#define EE 800000
#define DD 128

// ---------------- scratch (static device globals) ----------------
__device__ float g_aggr[(size_t)NN * DD];                 // 25.6 MB
__device__ float g_h[(size_t)NN * 2 * DD];                // 51.2 MB
__device__ float g_y0[(size_t)NN * DD];                   // 25.6 MB
__device__ __nv_bfloat16 g_Ahi[(size_t)NN * 2 * DD];      // 25.6 MB
__device__ __nv_bfloat16 g_Alo[(size_t)NN * 2 * DD];      // 25.6 MB
__device__ __nv_bfloat16 g_Wthi[256 * 256];
__device__ __nv_bfloat16 g_Wtlo[256 * 256];

// ---------------- PTX helpers (base ISA only, no tcgen05) ----------------
__device__ __forceinline__ uint32_t smem_u32(const void* p) {
    uint32_t a;
    asm("{ .reg .u64 t; cvta.to.shared.u64 t, %1; cvt.u32.u64 %0, t; }" : "=r"(a) : "l"(p));
    return a;
}
__device__ __forceinline__ void cp_async16(uint32_t dst, const void* src, int srcbytes) {
    asm volatile("cp.async.cg.shared.global [%0], [%1], 16, %2;"
                 :: "r"(dst), "l"(src), "r"(srcbytes) : "memory");
}
__device__ __forceinline__ void cp_commit() { asm volatile("cp.async.commit_group;" ::: "memory"); }
__device__ __forceinline__ void cp_wait0()  { asm volatile("cp.async.wait_group 0;" ::: "memory"); }

__device__ __forceinline__ void ldsm_x4(uint32_t& r0, uint32_t& r1, uint32_t& r2, uint32_t& r3,
                                        uint32_t addr) {
    asm volatile("ldmatrix.sync.aligned.m8n8.x4.shared.b16 {%0,%1,%2,%3}, [%4];"
                 : "=r"(r0), "=r"(r1), "=r"(r2), "=r"(r3) : "r"(addr));
}
__device__ __forceinline__ void mma16816(float* d, const uint32_t* a, const uint32_t* b) {
    asm volatile(
        "mma.sync.aligned.m16n8k16.row.col.f32.bf16.bf16.f32 "
        "{%0,%1,%2,%3}, {%4,%5,%6,%7}, {%8,%9}, {%0,%1,%2,%3};"
        : "+f"(d[0]), "+f"(d[1]), "+f"(d[2]), "+f"(d[3])
        : "r"(a[0]), "r"(a[1]), "r"(a[2]), "r"(a[3]), "r"(b[0]), "r"(b[1]));
}

// ---------------- zero kernel ----------------
__global__ void zero_kernel(float4* __restrict__ p, long n4) {
    long i = (long)blockIdx.x * blockDim.x + threadIdx.x;
    if (i < n4) p[i] = make_float4(0.f, 0.f, 0.f, 0.f);
}

// ---------------- scatter ----------------
__global__ void __launch_bounds__(256)
scatter_kernel(const float* __restrict__ x,
               const int* __restrict__ ei, const int* __restrict__ ea,
               const float* __restrict__ ee1, const float* __restrict__ ee2,
               float* __restrict__ aggr, int E) {
    long idx = (long)blockIdx.x * blockDim.x + threadIdx.x;
    int e = (int)(idx >> 5);
    if (e >= E) return;
    int lane = (int)(idx & 31);
    int d = lane * 4;

    int src = ei[e];
    int dst = ei[E + e];
    int a0 = ea[2 * e];
    int a1 = ea[2 * e + 1];

    float4 xv = *(const float4*)(x + (long)src * DD + d);
    float4 v1 = *(const float4*)(ee1 + a0 * DD + d);
    float4 v2 = *(const float4*)(ee2 + a1 * DD + d);

    float4 v;
    v.x = xv.x + v1.x + v2.x;
    v.y = xv.y + v1.y + v2.y;
    v.z = xv.z + v1.z + v2.z;
    v.w = xv.w + v1.w + v2.w;

    float* p = aggr + (long)dst * DD + d;
    asm volatile("red.global.add.v4.f32 [%0], {%1, %2, %3, %4};"
                 :: "l"(p), "f"(v.x), "f"(v.y), "f"(v.z), "f"(v.w) : "memory");
}

// ---------------- fp32 -> bf16 hi/lo split ----------------
__global__ void __launch_bounds__(256)
split_kernel(const float* __restrict__ in, __nv_bfloat16* __restrict__ hi,
             __nv_bfloat16* __restrict__ lo, long n) {
    long i = ((long)blockIdx.x * blockDim.x + threadIdx.x) * 4;
    if (i >= n) return;
    float4 v = *(const float4*)(in + i);
    __nv_bfloat16 h0 = __float2bfloat16_rn(v.x);
    __nv_bfloat16 h1 = __float2bfloat16_rn(v.y);
    __nv_bfloat16 h2 = __float2bfloat16_rn(v.z);
    __nv_bfloat16 h3 = __float2bfloat16_rn(v.w);
    __nv_bfloat16 l0 = __float2bfloat16_rn(v.x - __bfloat162float(h0));
    __nv_bfloat16 l1 = __float2bfloat16_rn(v.y - __bfloat162float(h1));
    __nv_bfloat16 l2 = __float2bfloat16_rn(v.z - __bfloat162float(h2));
    __nv_bfloat16 l3 = __float2bfloat16_rn(v.w - __bfloat162float(h3));
    *(__nv_bfloat162*)(hi + i)     = __nv_bfloat162(h0, h1);
    *(__nv_bfloat162*)(hi + i + 2) = __nv_bfloat162(h2, h3);
    *(__nv_bfloat162*)(lo + i)     = __nv_bfloat162(l0, l1);
    *(__nv_bfloat162*)(lo + i + 2) = __nv_bfloat162(l2, l3);
}

// ---------------- W [K,N] fp32 -> Wt [N,K] bf16 hi/lo ----------------
__global__ void __launch_bounds__(256)
wtrans_kernel(const float* __restrict__ W, __nv_bfloat16* __restrict__ thi,
              __nv_bfloat16* __restrict__ tlo, int K, int N) {
    int i = blockIdx.x * blockDim.x + threadIdx.x;
    if (i >= K * N) return;
    int k = i / N, n = i % N;
    float a = W[i];
    __nv_bfloat16 h = __float2bfloat16_rn(a);
    __nv_bfloat16 l = __float2bfloat16_rn(a - __bfloat162float(h));
    thi[(long)n * K + k] = h;
    tlo[(long)n * K + k] = l;
}

// ---------------- HMMA GEMM: C[M,Ntot] = act(A @ Wt^T + bias) ----------------
// A: [M,Ktot] bf16 hi/lo.  Wt: [Ntot,Ktot] bf16 hi/lo (K-contiguous rows).
// Block tile 128x128, 8 warps (warp tile 32x64), K-chunks of 128 via cp.async.
// SMEM rows padded to 136 bf16 (272B) for conflict-free ldmatrix.
#define SROWB 272                          // bytes per smem row
#define STILE (128 * SROWB)                // 34816 B per tile
#define GEMM_SMEM (4 * STILE)              // 139264 B

template <bool RELU>
__global__ void __launch_bounds__(256, 1)
gemm_mma(const __nv_bfloat16* __restrict__ Ahi, const __nv_bfloat16* __restrict__ Alo,
         const __nv_bfloat16* __restrict__ Bhi, const __nv_bfloat16* __restrict__ Blo,
         const float* __restrict__ bias, float* __restrict__ C,
         int M, int Ntot, int Ktot) {
    extern __shared__ char smem[];
    const uint32_t sb = smem_u32(smem);
    const uint32_t sAhi = sb;
    const uint32_t sAlo = sb + STILE;
    const uint32_t sBhi = sb + 2 * STILE;
    const uint32_t sBlo = sb + 3 * STILE;

    const int tid  = threadIdx.x;
    const int lane = tid & 31;
    const int wid  = tid >> 5;
    const int wm   = (wid & 3) * 32;   // warp row offset in tile
    const int wn   = (wid >> 2) * 64;  // warp col offset in tile
    const int brow = blockIdx.y * 128;
    const int bcol = blockIdx.x * 128;

    float acc[2][8][4];
#pragma unroll
    for (int i = 0; i < 2; i++)
#pragma unroll
        for (int j = 0; j < 8; j++)
#pragma unroll
            for (int k = 0; k < 4; k++) acc[i][j][k] = 0.f;

    const int kchunks = Ktot >> 7;
    for (int ch = 0; ch < kchunks; ch++) {
        const int kc = ch << 7;
        if (ch) __syncthreads();  // protect smem before overwrite

        // ---- stage A (hi/lo) and B (hi/lo): 128 rows x 256B each ----
#pragma unroll
        for (int i = 0; i < 8; i++) {
            int id = tid + i * 256;            // 0..2047
            int row = id >> 4, off = (id & 15) * 16;
            uint32_t sdst = (uint32_t)(row * SROWB + off);
            int asz = (brow + row) < M ? 16 : 0;
            const char* asrch = (const char*)(Ahi + (size_t)(brow + row) * Ktot + kc) + off;
            const char* asrcl = (const char*)(Alo + (size_t)(brow + row) * Ktot + kc) + off;
            cp_async16(sAhi + sdst, asrch, asz);
            cp_async16(sAlo + sdst, asrcl, asz);
            const char* bsrch = (const char*)(Bhi + (size_t)(bcol + row) * Ktot + kc) + off;
            const char* bsrcl = (const char*)(Blo + (size_t)(bcol + row) * Ktot + kc) + off;
            cp_async16(sBhi + sdst, bsrch, 16);
            cp_async16(sBlo + sdst, bsrcl, 16);
        }
        cp_commit();
        cp_wait0();
        __syncthreads();

        // ---- compute: 8 k-steps of 16 ----
#pragma unroll
        for (int kk = 0; kk < 8; kk++) {
            const uint32_t kb = (uint32_t)(kk * 32);  // 16 bf16 = 32B

            // A fragments: mt in {0,1}; lanes 0-15 rows, lanes 16-31 k+8 half
            uint32_t ah[2][4], al[2][4];
#pragma unroll
            for (int mt = 0; mt < 2; mt++) {
                uint32_t arow = (uint32_t)(wm + mt * 16 + (lane & 15));
                uint32_t aoff = arow * SROWB + kb + ((lane >> 4) << 4);
                ldsm_x4(ah[mt][0], ah[mt][1], ah[mt][2], ah[mt][3], sAhi + aoff);
                ldsm_x4(al[mt][0], al[mt][1], al[mt][2], al[mt][3], sAlo + aoff);
            }
            // B fragments: np pairs; x4 gives tiles np*2 (r0,r1) and np*2+1 (r2,r3)
            uint32_t bh[8][2], bl[8][2];
#pragma unroll
            for (int np = 0; np < 4; np++) {
                int g = lane >> 3, r = lane & 7;
                uint32_t browi = (uint32_t)(wn + np * 16 + ((g & 2) ? 8 : 0) + r);
                uint32_t boff = browi * SROWB + kb + ((g & 1) << 4);
                uint32_t r0, r1, r2, r3;
                ldsm_x4(r0, r1, r2, r3, sBhi + boff);
                bh[np * 2][0] = r0; bh[np * 2][1] = r1;
                bh[np * 2 + 1][0] = r2; bh[np * 2 + 1][1] = r3;
                ldsm_x4(r0, r1, r2, r3, sBlo + boff);
                bl[np * 2][0] = r0; bl[np * 2][1] = r1;
                bl[np * 2 + 1][0] = r2; bl[np * 2 + 1][1] = r3;
            }
            // 3-pass MMA: Ah*Bh + Ah*Bl + Al*Bh
#pragma unroll
            for (int mt = 0; mt < 2; mt++)
#pragma unroll
                for (int nt = 0; nt < 8; nt++) {
                    mma16816(acc[mt][nt], ah[mt], bh[nt]);
                    mma16816(acc[mt][nt], ah[mt], bl[nt]);
                    mma16816(acc[mt][nt], al[mt], bh[nt]);
                }
        }
    }

    // ---- epilogue: bias + optional relu, float2 stores ----
#pragma unroll
    for (int mt = 0; mt < 2; mt++) {
#pragma unroll
        for (int nt = 0; nt < 8; nt++) {
            int gcol = bcol + wn + nt * 8 + (lane & 3) * 2;
            float b0 = bias[gcol], b1 = bias[gcol + 1];
#pragma unroll
            for (int hrow = 0; hrow < 2; hrow++) {
                int grow = brow + wm + mt * 16 + (lane >> 2) + hrow * 8;
                if (grow < M) {
                    float o0 = acc[mt][nt][hrow * 2 + 0] + b0;
                    float o1 = acc[mt][nt][hrow * 2 + 1] + b1;
                    if (RELU) { o0 = fmaxf(o0, 0.f); o1 = fmaxf(o1, 0.f); }
                    *(float2*)(C + (size_t)grow * Ntot + gcol) = make_float2(o0, o1);
                }
            }
        }
    }
}

// ---------------- launch ----------------
extern "C" void kernel_launch(void* const* d_in, const int* in_sizes, int n_in,
                              void* d_out, int out_size) {
    const float* x     = (const float*)d_in[0];
    const int*   ei    = (const int*)d_in[1];
    const int*   ea    = (const int*)d_in[2];
    const float* ee1_0 = (const float*)d_in[3];
    const float* ee2_0 = (const float*)d_in[4];
    const float* W1_0  = (const float*)d_in[5];
    const float* b1_0  = (const float*)d_in[6];
    const float* W2_0  = (const float*)d_in[7];
    const float* b2_0  = (const float*)d_in[8];
    const float* ee1_1 = (const float*)d_in[9];
    const float* ee2_1 = (const float*)d_in[10];
    const float* W1_1  = (const float*)d_in[11];
    const float* b1_1  = (const float*)d_in[12];
    const float* W2_1  = (const float*)d_in[13];
    const float* b2_1  = (const float*)d_in[14];
    float* out = (float*)d_out;

    const int N = in_sizes[0] / DD;  // 50000
    const int E = in_sizes[1] / 2;   // 800000

    float *aggr, *h, *y0;
    __nv_bfloat16 *Ahi, *Alo, *Wthi, *Wtlo;
    cudaGetSymbolAddress((void**)&aggr, g_aggr);
    cudaGetSymbolAddress((void**)&h, g_h);
    cudaGetSymbolAddress((void**)&y0, g_y0);
    cudaGetSymbolAddress((void**)&Ahi, g_Ahi);
    cudaGetSymbolAddress((void**)&Alo, g_Alo);
    cudaGetSymbolAddress((void**)&Wthi, g_Wthi);
    cudaGetSymbolAddress((void**)&Wtlo, g_Wtlo);

    cudaFuncSetAttribute(gemm_mma<true>, cudaFuncAttributeMaxDynamicSharedMemorySize, GEMM_SMEM);
    cudaFuncSetAttribute(gemm_mma<false>, cudaFuncAttributeMaxDynamicSharedMemorySize, GEMM_SMEM);

    const long n4_aggr = (long)N * DD / 4;
    dim3 zgrid((unsigned)((n4_aggr + 255) / 256));
    const long sc_threads = (long)E * 32;
    dim3 sgrid((unsigned)((sc_threads + 255) / 256));

    const long nA = (long)N * DD;      // 6.4M
    const long nH = (long)N * 2 * DD;  // 12.8M
    dim3 spgridA((unsigned)((nA / 4 + 255) / 256));
    dim3 spgridH((unsigned)((nH / 4 + 255) / 256));
    dim3 wgrid((256 * 256 + 255) / 256);

    const int MT = (N + 127) / 128;  // 391
    dim3 g1grid(2, MT);              // N_out = 256
    dim3 g2grid(1, MT);              // N_out = 128

    // ============ layer 0 ============
    zero_kernel<<<zgrid, 256>>>((float4*)aggr, n4_aggr);
    scatter_kernel<<<sgrid, 256>>>(x, ei, ea, ee1_0, ee2_0, aggr, E);
    split_kernel<<<spgridA, 256>>>(aggr, Ahi, Alo, nA);
    wtrans_kernel<<<wgrid, 256>>>(W1_0, Wthi, Wtlo, DD, 2 * DD);
    gemm_mma<true><<<g1grid, 256, GEMM_SMEM>>>(Ahi, Alo, Wthi, Wtlo, b1_0, h, N, 2 * DD, DD);
    split_kernel<<<spgridH, 256>>>(h, Ahi, Alo, nH);
    wtrans_kernel<<<wgrid, 256>>>(W2_0, Wthi, Wtlo, 2 * DD, DD);
    gemm_mma<true><<<g2grid, 256, GEMM_SMEM>>>(Ahi, Alo, Wthi, Wtlo, b2_0, y0, N, DD, 2 * DD);

    // ============ layer 1 ============
    zero_kernel<<<zgrid, 256>>>((float4*)aggr, n4_aggr);
    scatter_kernel<<<sgrid, 256>>>(y0, ei, ea, ee1_1, ee2_1, aggr, E);
    split_kernel<<<spgridA, 256>>>(aggr, Ahi, Alo, nA);
    wtrans_kernel<<<wgrid, 256>>>(W1_1, Wthi, Wtlo, DD, 2 * DD);
    gemm_mma<true><<<g1grid, 256, GEMM_SMEM>>>(Ahi, Alo, Wthi, Wtlo, b1_1, h, N, 2 * DD, DD);
    split_kernel<<<spgridH, 256>>>(h, Ahi, Alo, nH);
    wtrans_kernel<<<wgrid, 256>>>(W2_1, Wthi, Wtlo, 2 * DD, DD);
    gemm_mma<false><<<g2grid, 256, GEMM_SMEM>>>(Ahi, Alo, Wthi, Wtlo, b2_1, out, N, DD, 2 * DD);
}

// round 4
// speedup vs baseline: 1.4762x; 1.0455x over previous
#include <cuda_runtime.h>
#include <cuda_bf16.h>
#include <cstdint>

#define NN 50000
#define EE 800000
#define DD 128

// ---------------- scratch (static device globals) ----------------
__device__ float g_aggr[(size_t)NN * DD];                 // 25.6 MB
__device__ float g_y0[(size_t)NN * DD];                   // 25.6 MB
__device__ __nv_bfloat16 g_Hhi[(size_t)NN * 2 * DD];      // 25.6 MB
__device__ __nv_bfloat16 g_Hlo[(size_t)NN * 2 * DD];      // 25.6 MB
// transposed weights, hi/lo: W1 -> [256,128], W2 -> [128,256]
__device__ __nv_bfloat16 g_Wt[8][256 * 128];

// ---------------- PTX helpers (base ISA only) ----------------
__device__ __forceinline__ uint32_t smem_u32(const void* p) {
    uint32_t a;
    asm("{ .reg .u64 t; cvta.to.shared.u64 t, %1; cvt.u32.u64 %0, t; }" : "=r"(a) : "l"(p));
    return a;
}
__device__ __forceinline__ void cp_async16(uint32_t dst, const void* src, int srcbytes) {
    asm volatile("cp.async.cg.shared.global [%0], [%1], 16, %2;"
                 :: "r"(dst), "l"(src), "r"(srcbytes) : "memory");
}
__device__ __forceinline__ void cp_commit() { asm volatile("cp.async.commit_group;" ::: "memory"); }
__device__ __forceinline__ void cp_wait0()  { asm volatile("cp.async.wait_group 0;" ::: "memory"); }

__device__ __forceinline__ void ldsm_x4(uint32_t& r0, uint32_t& r1, uint32_t& r2, uint32_t& r3,
                                        uint32_t addr) {
    asm volatile("ldmatrix.sync.aligned.m8n8.x4.shared.b16 {%0,%1,%2,%3}, [%4];"
                 : "=r"(r0), "=r"(r1), "=r"(r2), "=r"(r3) : "r"(addr));
}
__device__ __forceinline__ void mma16816(float* d, const uint32_t* a, const uint32_t* b) {
    asm volatile(
        "mma.sync.aligned.m16n8k16.row.col.f32.bf16.bf16.f32 "
        "{%0,%1,%2,%3}, {%4,%5,%6,%7}, {%8,%9}, {%0,%1,%2,%3};"
        : "+f"(d[0]), "+f"(d[1]), "+f"(d[2]), "+f"(d[3])
        : "r"(a[0]), "r"(a[1]), "r"(a[2]), "r"(a[3]), "r"(b[0]), "r"(b[1]));
}

// ---------------- zero kernel ----------------
__global__ void zero_kernel(float4* __restrict__ p, long n4) {
    long i = (long)blockIdx.x * blockDim.x + threadIdx.x;
    if (i < n4) p[i] = make_float4(0.f, 0.f, 0.f, 0.f);
}

// ---------------- scatter ----------------
__global__ void __launch_bounds__(256)
scatter_kernel(const float* __restrict__ x,
               const int* __restrict__ ei, const int* __restrict__ ea,
               const float* __restrict__ ee1, const float* __restrict__ ee2,
               float* __restrict__ aggr, int E) {
    long idx = (long)blockIdx.x * blockDim.x + threadIdx.x;
    int e = (int)(idx >> 5);
    if (e >= E) return;
    int lane = (int)(idx & 31);
    int d = lane * 4;

    int src = ei[e];
    int dst = ei[E + e];
    int a0 = ea[2 * e];
    int a1 = ea[2 * e + 1];

    float4 xv = *(const float4*)(x + (long)src * DD + d);
    float4 v1 = *(const float4*)(ee1 + a0 * DD + d);
    float4 v2 = *(const float4*)(ee2 + a1 * DD + d);

    float4 v;
    v.x = xv.x + v1.x + v2.x;
    v.y = xv.y + v1.y + v2.y;
    v.z = xv.z + v1.z + v2.z;
    v.w = xv.w + v1.w + v2.w;

    float* p = aggr + (long)dst * DD + d;
    asm volatile("red.global.add.v4.f32 [%0], {%1, %2, %3, %4};"
                 :: "l"(p), "f"(v.x), "f"(v.y), "f"(v.z), "f"(v.w) : "memory");
}

// ---------------- all 4 weight transposes in one launch ----------------
// which 0: W1_0 [128,256]; 1: W2_0 [256,128]; 2: W1_1; 3: W2_1
__global__ void __launch_bounds__(256)
wtrans_all(const float* __restrict__ W10, const float* __restrict__ W20,
           const float* __restrict__ W11, const float* __restrict__ W21,
           __nv_bfloat16* __restrict__ wt /* g_Wt base: [8][32768] */) {
    int which = blockIdx.x >> 7;             // 128 blocks per matrix
    int i = ((blockIdx.x & 127) << 8) + threadIdx.x;  // 0..32767
    const float* W;
    int K, N;
    if (which == 0)      { W = W10; K = 128; N = 256; }
    else if (which == 1) { W = W20; K = 256; N = 128; }
    else if (which == 2) { W = W11; K = 128; N = 256; }
    else                 { W = W21; K = 256; N = 128; }
    int k = i / N, n = i % N;
    float a = W[i];
    __nv_bfloat16 h = __float2bfloat16_rn(a);
    __nv_bfloat16 l = __float2bfloat16_rn(a - __bfloat162float(h));
    __nv_bfloat16* thi = wt + (size_t)(2 * which) * 32768;
    __nv_bfloat16* tlo = thi + 32768;
    thi[n * K + k] = h;
    tlo[n * K + k] = l;
}

// ---------------- common tiling constants ----------------
#define SROWB 272                     // bytes per smem row (136 bf16)
#define STILE (128 * SROWB)           // 34816 B per tile
#define GEMM_SMEM (4 * STILE)         // 139264 B

// ---------------- GEMM1: H = relu(Afp32 @ Wt1^T + b1), H emitted as bf16 hi/lo ----
// A: [M,128] fp32 (in-kernel hi/lo split). Wt1: [256,128] bf16 hi/lo. Ntot=256 fixed.
__global__ void __launch_bounds__(256, 1)
gemm1_f32A(const float* __restrict__ A,
           const __nv_bfloat16* __restrict__ Bhi, const __nv_bfloat16* __restrict__ Blo,
           const float* __restrict__ bias,
           __nv_bfloat16* __restrict__ Hhi, __nv_bfloat16* __restrict__ Hlo,
           int M) {
    extern __shared__ char smem[];
    const uint32_t sb = smem_u32(smem);
    const uint32_t sAhi = sb;
    const uint32_t sAlo = sb + STILE;
    const uint32_t sBhi = sb + 2 * STILE;
    const uint32_t sBlo = sb + 3 * STILE;

    const int tid  = threadIdx.x;
    const int lane = tid & 31;
    const int wid  = tid >> 5;
    const int wm   = (wid & 3) * 32;
    const int wn   = (wid >> 2) * 64;
    const int brow = blockIdx.y * 128;
    const int bcol = blockIdx.x * 128;

    // ---- B tiles via cp.async: 128 rows x 256B (K=128 bf16) ----
#pragma unroll
    for (int i = 0; i < 8; i++) {
        int id = tid + i * 256;
        int row = id >> 4, off = (id & 15) * 16;
        uint32_t sdst = (uint32_t)(row * SROWB + off);
        const char* bh = (const char*)(Bhi + (size_t)(bcol + row) * 128) + off;
        const char* bl = (const char*)(Blo + (size_t)(bcol + row) * 128) + off;
        cp_async16(sBhi + sdst, bh, 16);
        cp_async16(sBlo + sdst, bl, 16);
    }
    cp_commit();

    // ---- A: LDG fp32 -> convert -> STS hi/lo ----
#pragma unroll
    for (int i = 0; i < 16; i++) {
        int id = tid + i * 256;          // 0..4095 = 128 rows x 32 f4
        int row = id >> 5, f4 = id & 31;
        float4 v = make_float4(0.f, 0.f, 0.f, 0.f);
        if (brow + row < M) v = *(const float4*)(A + (size_t)(brow + row) * 128 + f4 * 4);
        __nv_bfloat16 h0 = __float2bfloat16_rn(v.x), h1 = __float2bfloat16_rn(v.y);
        __nv_bfloat16 h2 = __float2bfloat16_rn(v.z), h3 = __float2bfloat16_rn(v.w);
        __nv_bfloat16 l0 = __float2bfloat16_rn(v.x - __bfloat162float(h0));
        __nv_bfloat16 l1 = __float2bfloat16_rn(v.y - __bfloat162float(h1));
        __nv_bfloat16 l2 = __float2bfloat16_rn(v.z - __bfloat162float(h2));
        __nv_bfloat16 l3 = __float2bfloat16_rn(v.w - __bfloat162float(h3));
        __nv_bfloat162 hp0(h0, h1), hp1(h2, h3), lp0(l0, l1), lp1(l2, l3);
        uint2 hv = make_uint2(*(uint32_t*)&hp0, *(uint32_t*)&hp1);
        uint2 lv = make_uint2(*(uint32_t*)&lp0, *(uint32_t*)&lp1);
        uint32_t sdst = (uint32_t)(row * SROWB + f4 * 8);
        *(uint2*)(smem + (sAhi - sb) + sdst) = hv;
        *(uint2*)(smem + (sAlo - sb) + sdst) = lv;
    }
    cp_wait0();
    __syncthreads();

    float acc[2][8][4];
#pragma unroll
    for (int i = 0; i < 2; i++)
#pragma unroll
        for (int j = 0; j < 8; j++)
#pragma unroll
            for (int k = 0; k < 4; k++) acc[i][j][k] = 0.f;

    // ---- compute: 8 k-steps of 16 (single K=128 chunk) ----
#pragma unroll
    for (int kk = 0; kk < 8; kk++) {
        const uint32_t kb = (uint32_t)(kk * 32);
        uint32_t ah[2][4], al[2][4];
#pragma unroll
        for (int mt = 0; mt < 2; mt++) {
            uint32_t arow = (uint32_t)(wm + mt * 16 + (lane & 15));
            uint32_t aoff = arow * SROWB + kb + ((lane >> 4) << 4);
            ldsm_x4(ah[mt][0], ah[mt][1], ah[mt][2], ah[mt][3], sAhi + aoff);
            ldsm_x4(al[mt][0], al[mt][1], al[mt][2], al[mt][3], sAlo + aoff);
        }
        uint32_t bh[8][2], bl[8][2];
#pragma unroll
        for (int np = 0; np < 4; np++) {
            int g = lane >> 3, r = lane & 7;
            uint32_t browi = (uint32_t)(wn + np * 16 + ((g & 2) ? 8 : 0) + r);
            uint32_t boff = browi * SROWB + kb + ((g & 1) << 4);
            uint32_t r0, r1, r2, r3;
            ldsm_x4(r0, r1, r2, r3, sBhi + boff);
            bh[np * 2][0] = r0; bh[np * 2][1] = r1;
            bh[np * 2 + 1][0] = r2; bh[np * 2 + 1][1] = r3;
            ldsm_x4(r0, r1, r2, r3, sBlo + boff);
            bl[np * 2][0] = r0; bl[np * 2][1] = r1;
            bl[np * 2 + 1][0] = r2; bl[np * 2 + 1][1] = r3;
        }
#pragma unroll
        for (int mt = 0; mt < 2; mt++)
#pragma unroll
            for (int nt = 0; nt < 8; nt++) {
                mma16816(acc[mt][nt], ah[mt], bh[nt]);
                mma16816(acc[mt][nt], ah[mt], bl[nt]);
                mma16816(acc[mt][nt], al[mt], bh[nt]);
            }
    }

    // ---- epilogue: bias + relu, split to bf16 hi/lo, store ----
#pragma unroll
    for (int mt = 0; mt < 2; mt++) {
#pragma unroll
        for (int nt = 0; nt < 8; nt++) {
            int gcol = bcol + wn + nt * 8 + (lane & 3) * 2;
            float b0 = bias[gcol], b1 = bias[gcol + 1];
#pragma unroll
            for (int hrow = 0; hrow < 2; hrow++) {
                int grow = brow + wm + mt * 16 + (lane >> 2) + hrow * 8;
                if (grow < M) {
                    float o0 = fmaxf(acc[mt][nt][hrow * 2 + 0] + b0, 0.f);
                    float o1 = fmaxf(acc[mt][nt][hrow * 2 + 1] + b1, 0.f);
                    __nv_bfloat16 h0 = __float2bfloat16_rn(o0);
                    __nv_bfloat16 h1 = __float2bfloat16_rn(o1);
                    __nv_bfloat16 l0 = __float2bfloat16_rn(o0 - __bfloat162float(h0));
                    __nv_bfloat16 l1 = __float2bfloat16_rn(o1 - __bfloat162float(h1));
                    __nv_bfloat162 hp(h0, h1), lp(l0, l1);
                    size_t o = (size_t)grow * 256 + gcol;
                    *(__nv_bfloat162*)(Hhi + o) = hp;
                    *(__nv_bfloat162*)(Hlo + o) = lp;
                }
            }
        }
    }
}

// ---------------- GEMM2: C = act(Hbf16 @ Wt2^T + b2), fp32 out ----------------
// A: [M,256] bf16 hi/lo. Wt2: [128,256] bf16 hi/lo. Ntot=128, Ktot=256 fixed.
template <bool RELU>
__global__ void __launch_bounds__(256, 1)
gemm2_bfA(const __nv_bfloat16* __restrict__ Ahi, const __nv_bfloat16* __restrict__ Alo,
          const __nv_bfloat16* __restrict__ Bhi, const __nv_bfloat16* __restrict__ Blo,
          const float* __restrict__ bias, float* __restrict__ C, int M) {
    extern __shared__ char smem[];
    const uint32_t sb = smem_u32(smem);
    const uint32_t sAhi = sb;
    const uint32_t sAlo = sb + STILE;
    const uint32_t sBhi = sb + 2 * STILE;
    const uint32_t sBlo = sb + 3 * STILE;

    const int tid  = threadIdx.x;
    const int lane = tid & 31;
    const int wid  = tid >> 5;
    const int wm   = (wid & 3) * 32;
    const int wn   = (wid >> 2) * 64;
    const int brow = blockIdx.y * 128;
    const int bcol = blockIdx.x * 128;
    const int Ktot = 256;

    float acc[2][8][4];
#pragma unroll
    for (int i = 0; i < 2; i++)
#pragma unroll
        for (int j = 0; j < 8; j++)
#pragma unroll
            for (int k = 0; k < 4; k++) acc[i][j][k] = 0.f;

#pragma unroll
    for (int ch = 0; ch < 2; ch++) {
        const int kc = ch << 7;
        if (ch) __syncthreads();
#pragma unroll
        for (int i = 0; i < 8; i++) {
            int id = tid + i * 256;
            int row = id >> 4, off = (id & 15) * 16;
            uint32_t sdst = (uint32_t)(row * SROWB + off);
            int asz = (brow + row) < M ? 16 : 0;
            const char* ah = (const char*)(Ahi + (size_t)(brow + row) * Ktot + kc) + off;
            const char* al = (const char*)(Alo + (size_t)(brow + row) * Ktot + kc) + off;
            cp_async16(sAhi + sdst, ah, asz);
            cp_async16(sAlo + sdst, al, asz);
            const char* bh = (const char*)(Bhi + (size_t)(bcol + row) * Ktot + kc) + off;
            const char* bl = (const char*)(Blo + (size_t)(bcol + row) * Ktot + kc) + off;
            cp_async16(sBhi + sdst, bh, 16);
            cp_async16(sBlo + sdst, bl, 16);
        }
        cp_commit();
        cp_wait0();
        __syncthreads();

#pragma unroll
        for (int kk = 0; kk < 8; kk++) {
            const uint32_t kb = (uint32_t)(kk * 32);
            uint32_t ah[2][4], al[2][4];
#pragma unroll
            for (int mt = 0; mt < 2; mt++) {
                uint32_t arow = (uint32_t)(wm + mt * 16 + (lane & 15));
                uint32_t aoff = arow * SROWB + kb + ((lane >> 4) << 4);
                ldsm_x4(ah[mt][0], ah[mt][1], ah[mt][2], ah[mt][3], sAhi + aoff);
                ldsm_x4(al[mt][0], al[mt][1], al[mt][2], al[mt][3], sAlo + aoff);
            }
            uint32_t bh[8][2], bl[8][2];
#pragma unroll
            for (int np = 0; np < 4; np++) {
                int g = lane >> 3, r = lane & 7;
                uint32_t browi = (uint32_t)(wn + np * 16 + ((g & 2) ? 8 : 0) + r);
                uint32_t boff = browi * SROWB + kb + ((g & 1) << 4);
                uint32_t r0, r1, r2, r3;
                ldsm_x4(r0, r1, r2, r3, sBhi + boff);
                bh[np * 2][0] = r0; bh[np * 2][1] = r1;
                bh[np * 2 + 1][0] = r2; bh[np * 2 + 1][1] = r3;
                ldsm_x4(r0, r1, r2, r3, sBlo + boff);
                bl[np * 2][0] = r0; bl[np * 2][1] = r1;
                bl[np * 2 + 1][0] = r2; bl[np * 2 + 1][1] = r3;
            }
#pragma unroll
            for (int mt = 0; mt < 2; mt++)
#pragma unroll
                for (int nt = 0; nt < 8; nt++) {
                    mma16816(acc[mt][nt], ah[mt], bh[nt]);
                    mma16816(acc[mt][nt], ah[mt], bl[nt]);
                    mma16816(acc[mt][nt], al[mt], bh[nt]);
                }
        }
    }

#pragma unroll
    for (int mt = 0; mt < 2; mt++) {
#pragma unroll
        for (int nt = 0; nt < 8; nt++) {
            int gcol = bcol + wn + nt * 8 + (lane & 3) * 2;
            float b0 = bias[gcol], b1 = bias[gcol + 1];
#pragma unroll
            for (int hrow = 0; hrow < 2; hrow++) {
                int grow = brow + wm + mt * 16 + (lane >> 2) + hrow * 8;
                if (grow < M) {
                    float o0 = acc[mt][nt][hrow * 2 + 0] + b0;
                    float o1 = acc[mt][nt][hrow * 2 + 1] + b1;
                    if (RELU) { o0 = fmaxf(o0, 0.f); o1 = fmaxf(o1, 0.f); }
                    *(float2*)(C + (size_t)grow * 128 + gcol) = make_float2(o0, o1);
                }
            }
        }
    }
}

// ---------------- launch ----------------
extern "C" void kernel_launch(void* const* d_in, const int* in_sizes, int n_in,
                              void* d_out, int out_size) {
    const float* x     = (const float*)d_in[0];
    const int*   ei    = (const int*)d_in[1];
    const int*   ea    = (const int*)d_in[2];
    const float* ee1_0 = (const float*)d_in[3];
    const float* ee2_0 = (const float*)d_in[4];
    const float* W1_0  = (const float*)d_in[5];
    const float* b1_0  = (const float*)d_in[6];
    const float* W2_0  = (const float*)d_in[7];
    const float* b2_0  = (const float*)d_in[8];
    const float* ee1_1 = (const float*)d_in[9];
    const float* ee2_1 = (const float*)d_in[10];
    const float* W1_1  = (const float*)d_in[11];
    const float* b1_1  = (const float*)d_in[12];
    const float* W2_1  = (const float*)d_in[13];
    const float* b2_1  = (const float*)d_in[14];
    float* out = (float*)d_out;

    const int N = in_sizes[0] / DD;  // 50000
    const int E = in_sizes[1] / 2;   // 800000

    float *aggr, *y0;
    __nv_bfloat16 *Hhi, *Hlo, *Wt;
    cudaGetSymbolAddress((void**)&aggr, g_aggr);
    cudaGetSymbolAddress((void**)&y0, g_y0);
    cudaGetSymbolAddress((void**)&Hhi, g_Hhi);
    cudaGetSymbolAddress((void**)&Hlo, g_Hlo);
    cudaGetSymbolAddress((void**)&Wt, g_Wt);

    cudaFuncSetAttribute(gemm1_f32A, cudaFuncAttributeMaxDynamicSharedMemorySize, GEMM_SMEM);
    cudaFuncSetAttribute(gemm2_bfA<true>, cudaFuncAttributeMaxDynamicSharedMemorySize, GEMM_SMEM);
    cudaFuncSetAttribute(gemm2_bfA<false>, cudaFuncAttributeMaxDynamicSharedMemorySize, GEMM_SMEM);

    const long n4_aggr = (long)N * DD / 4;
    dim3 zgrid((unsigned)((n4_aggr + 255) / 256));
    const long sc_threads = (long)E * 32;
    dim3 sgrid((unsigned)((sc_threads + 255) / 256));

    const int MT = (N + 127) / 128;  // 391
    dim3 g1grid(2, MT);              // Ntot = 256
    dim3 g2grid(1, MT);              // Ntot = 128

    // Wt[0,1]=W1_0 hi/lo, [2,3]=W2_0, [4,5]=W1_1, [6,7]=W2_1
    wtrans_all<<<512, 256>>>(W1_0, W2_0, W1_1, W2_1, Wt);

    // ============ layer 0 ============
    zero_kernel<<<zgrid, 256>>>((float4*)aggr, n4_aggr);
    scatter_kernel<<<sgrid, 256>>>(x, ei, ea, ee1_0, ee2_0, aggr, E);
    gemm1_f32A<<<g1grid, 256, GEMM_SMEM>>>(aggr, Wt + 0 * 32768, Wt + 1 * 32768, b1_0, Hhi, Hlo, N);
    gemm2_bfA<true><<<g2grid, 256, GEMM_SMEM>>>(Hhi, Hlo, Wt + 2 * 32768, Wt + 3 * 32768, b2_0, y0, N);

    // ============ layer 1 ============
    zero_kernel<<<zgrid, 256>>>((float4*)aggr, n4_aggr);
    scatter_kernel<<<sgrid, 256>>>(y0, ei, ea, ee1_1, ee2_1, aggr, E);
    gemm1_f32A<<<g1grid, 256, GEMM_SMEM>>>(aggr, Wt + 4 * 32768, Wt + 5 * 32768, b1_1, Hhi, Hlo, N);
    gemm2_bfA<false><<<g2grid, 256, GEMM_SMEM>>>(Hhi, Hlo, Wt + 6 * 32768, Wt + 7 * 32768, b2_1, out, N);
}

// round 5
// speedup vs baseline: 1.5738x; 1.0661x over previous
#include <cuda_runtime.h>
#include <cuda_bf16.h>
#include <cstdint>

#define NN 50000
#define EE 800000
#define DD 128

// ---------------- scratch (static device globals) ----------------
__device__ float g_aggr[(size_t)NN * DD];                 // 25.6 MB
__device__ float g_y0[(size_t)NN * DD];                   // 25.6 MB
__device__ __nv_bfloat16 g_Hhi[(size_t)NN * 2 * DD];      // 25.6 MB
__device__ __nv_bfloat16 g_Hlo[(size_t)NN * 2 * DD];      // 25.6 MB
__device__ __nv_bfloat16 g_Wt[8][256 * 128];

// ---------------- PTX helpers (base ISA only) ----------------
__device__ __forceinline__ uint32_t smem_u32(const void* p) {
    uint32_t a;
    asm("{ .reg .u64 t; cvta.to.shared.u64 t, %1; cvt.u32.u64 %0, t; }" : "=r"(a) : "l"(p));
    return a;
}
__device__ __forceinline__ void cp_async16(uint32_t dst, const void* src, int srcbytes) {
    asm volatile("cp.async.cg.shared.global [%0], [%1], 16, %2;"
                 :: "r"(dst), "l"(src), "r"(srcbytes) : "memory");
}
__device__ __forceinline__ void cp_commit() { asm volatile("cp.async.commit_group;" ::: "memory"); }
__device__ __forceinline__ void cp_wait0()  { asm volatile("cp.async.wait_group 0;" ::: "memory"); }

__device__ __forceinline__ void ldsm_x4(uint32_t& r0, uint32_t& r1, uint32_t& r2, uint32_t& r3,
                                        uint32_t addr) {
    asm volatile("ldmatrix.sync.aligned.m8n8.x4.shared.b16 {%0,%1,%2,%3}, [%4];"
                 : "=r"(r0), "=r"(r1), "=r"(r2), "=r"(r3) : "r"(addr));
}
__device__ __forceinline__ void mma16816(float* d, const uint32_t* a, const uint32_t* b) {
    asm volatile(
        "mma.sync.aligned.m16n8k16.row.col.f32.bf16.bf16.f32 "
        "{%0,%1,%2,%3}, {%4,%5,%6,%7}, {%8,%9}, {%0,%1,%2,%3};"
        : "+f"(d[0]), "+f"(d[1]), "+f"(d[2]), "+f"(d[3])
        : "r"(a[0]), "r"(a[1]), "r"(a[2]), "r"(a[3]), "r"(b[0]), "r"(b[1]));
}

// ---------------- zero kernel ----------------
__global__ void zero_kernel(float4* __restrict__ p, long n4) {
    long i = (long)blockIdx.x * blockDim.x + threadIdx.x;
    if (i < n4) p[i] = make_float4(0.f, 0.f, 0.f, 0.f);
}

// ---------------- prep: zero aggr + all 4 weight transposes, one launch ------
#define ZBLOCKS 6250  /* (50000*128/4)/256 */
__global__ void __launch_bounds__(256)
prep_kernel(float4* __restrict__ aggr4, long n4,
            const float* __restrict__ W10, const float* __restrict__ W20,
            const float* __restrict__ W11, const float* __restrict__ W21,
            __nv_bfloat16* __restrict__ wt) {
    long b = blockIdx.x;
    if (b < ZBLOCKS) {
        long i = b * blockDim.x + threadIdx.x;
        if (i < n4) aggr4[i] = make_float4(0.f, 0.f, 0.f, 0.f);
        return;
    }
    int bb = (int)(b - ZBLOCKS);                 // 0..511
    int which = bb >> 7;                         // 128 blocks per matrix
    int i = ((bb & 127) << 8) + threadIdx.x;     // 0..32767
    const float* W;
    int K, N;
    if (which == 0)      { W = W10; K = 128; N = 256; }
    else if (which == 1) { W = W20; K = 256; N = 128; }
    else if (which == 2) { W = W11; K = 128; N = 256; }
    else                 { W = W21; K = 256; N = 128; }
    int k = i / N, n = i % N;
    float a = W[i];
    __nv_bfloat16 h = __float2bfloat16_rn(a);
    __nv_bfloat16 l = __float2bfloat16_rn(a - __bfloat162float(h));
    __nv_bfloat16* thi = wt + (size_t)(2 * which) * 32768;
    __nv_bfloat16* tlo = thi + 32768;
    thi[n * K + k] = h;
    tlo[n * K + k] = l;
}

// ---------------- scatter ----------------
__global__ void __launch_bounds__(256)
scatter_kernel(const float* __restrict__ x,
               const int* __restrict__ ei, const int* __restrict__ ea,
               const float* __restrict__ ee1, const float* __restrict__ ee2,
               float* __restrict__ aggr, int E) {
    long idx = (long)blockIdx.x * blockDim.x + threadIdx.x;
    int e = (int)(idx >> 5);
    if (e >= E) return;
    int lane = (int)(idx & 31);
    int d = lane * 4;

    int src = ei[e];
    int dst = ei[E + e];
    int a0 = ea[2 * e];
    int a1 = ea[2 * e + 1];

    float4 xv = *(const float4*)(x + (long)src * DD + d);
    float4 v1 = *(const float4*)(ee1 + a0 * DD + d);
    float4 v2 = *(const float4*)(ee2 + a1 * DD + d);

    float4 v;
    v.x = xv.x + v1.x + v2.x;
    v.y = xv.y + v1.y + v2.y;
    v.z = xv.z + v1.z + v2.z;
    v.w = xv.w + v1.w + v2.w;

    float* p = aggr + (long)dst * DD + d;
    asm volatile("red.global.add.v4.f32 [%0], {%1, %2, %3, %4};"
                 :: "l"(p), "f"(v.x), "f"(v.y), "f"(v.z), "f"(v.w) : "memory");
}

// ---------------- tiling constants: BM=64, BN=128, 2 CTAs/SM ----------------
#define SROWB 272                     // bytes per smem row (136 bf16)
#define ATILE (64 * SROWB)            // 17408 B
#define BTILE (128 * SROWB)           // 34816 B
#define GEMM_SMEM (2 * ATILE + 2 * BTILE)  // 104448 B

// ---------------- GEMM1: H = relu(Afp32 @ Wt1^T + b1), H as bf16 hi/lo ------
// A: [M,128] fp32 (in-kernel split). Wt1: [256,128] bf16 hi/lo. Ntot=256.
// Warp grid 2(M) x 4(N), warp tile 32x32.
__global__ void __launch_bounds__(256, 2)
gemm1_f32A(const float* __restrict__ A,
           const __nv_bfloat16* __restrict__ Bhi, const __nv_bfloat16* __restrict__ Blo,
           const float* __restrict__ bias,
           __nv_bfloat16* __restrict__ Hhi, __nv_bfloat16* __restrict__ Hlo,
           int M) {
    extern __shared__ char smem[];
    const uint32_t sb = smem_u32(smem);
    const uint32_t sAhi = sb;
    const uint32_t sAlo = sb + ATILE;
    const uint32_t sBhi = sb + 2 * ATILE;
    const uint32_t sBlo = sb + 2 * ATILE + BTILE;

    const int tid  = threadIdx.x;
    const int lane = tid & 31;
    const int wid  = tid >> 5;
    const int wm   = (wid & 1) * 32;
    const int wn   = (wid >> 1) * 32;
    const int brow = blockIdx.y * 64;
    const int bcol = blockIdx.x * 128;

    // ---- B tiles via cp.async: 128 rows x 256B ----
#pragma unroll
    for (int i = 0; i < 8; i++) {
        int id = tid + i * 256;
        int row = id >> 4, off = (id & 15) * 16;
        uint32_t sdst = (uint32_t)(row * SROWB + off);
        const char* bh = (const char*)(Bhi + (size_t)(bcol + row) * 128) + off;
        const char* bl = (const char*)(Blo + (size_t)(bcol + row) * 128) + off;
        cp_async16(sBhi + sdst, bh, 16);
        cp_async16(sBlo + sdst, bl, 16);
    }
    cp_commit();

    // ---- A: LDG fp32 -> convert -> STS hi/lo (64 rows x 32 f4) ----
#pragma unroll
    for (int i = 0; i < 8; i++) {
        int id = tid + i * 256;          // 0..2047
        int row = id >> 5, f4 = id & 31;
        float4 v = make_float4(0.f, 0.f, 0.f, 0.f);
        if (brow + row < M) v = *(const float4*)(A + (size_t)(brow + row) * 128 + f4 * 4);
        __nv_bfloat16 h0 = __float2bfloat16_rn(v.x), h1 = __float2bfloat16_rn(v.y);
        __nv_bfloat16 h2 = __float2bfloat16_rn(v.z), h3 = __float2bfloat16_rn(v.w);
        __nv_bfloat16 l0 = __float2bfloat16_rn(v.x - __bfloat162float(h0));
        __nv_bfloat16 l1 = __float2bfloat16_rn(v.y - __bfloat162float(h1));
        __nv_bfloat16 l2 = __float2bfloat16_rn(v.z - __bfloat162float(h2));
        __nv_bfloat16 l3 = __float2bfloat16_rn(v.w - __bfloat162float(h3));
        __nv_bfloat162 hp0(h0, h1), hp1(h2, h3), lp0(l0, l1), lp1(l2, l3);
        uint2 hv = make_uint2(*(uint32_t*)&hp0, *(uint32_t*)&hp1);
        uint2 lv = make_uint2(*(uint32_t*)&lp0, *(uint32_t*)&lp1);
        uint32_t sdst = (uint32_t)(row * SROWB + f4 * 8);
        *(uint2*)(smem + sdst) = hv;
        *(uint2*)(smem + ATILE + sdst) = lv;
    }
    cp_wait0();
    __syncthreads();

    float acc[2][4][4];
#pragma unroll
    for (int i = 0; i < 2; i++)
#pragma unroll
        for (int j = 0; j < 4; j++)
#pragma unroll
            for (int k = 0; k < 4; k++) acc[i][j][k] = 0.f;

#pragma unroll
    for (int kk = 0; kk < 8; kk++) {
        const uint32_t kb = (uint32_t)(kk * 32);
        uint32_t ah[2][4], al[2][4];
#pragma unroll
        for (int mt = 0; mt < 2; mt++) {
            uint32_t arow = (uint32_t)(wm + mt * 16 + (lane & 15));
            uint32_t aoff = arow * SROWB + kb + ((lane >> 4) << 4);
            ldsm_x4(ah[mt][0], ah[mt][1], ah[mt][2], ah[mt][3], sAhi + aoff);
            ldsm_x4(al[mt][0], al[mt][1], al[mt][2], al[mt][3], sAlo + aoff);
        }
        uint32_t bh[4][2], bl[4][2];
#pragma unroll
        for (int np = 0; np < 2; np++) {
            int g = lane >> 3, r = lane & 7;
            uint32_t browi = (uint32_t)(wn + np * 16 + ((g & 2) ? 8 : 0) + r);
            uint32_t boff = browi * SROWB + kb + ((g & 1) << 4);
            uint32_t r0, r1, r2, r3;
            ldsm_x4(r0, r1, r2, r3, sBhi + boff);
            bh[np * 2][0] = r0; bh[np * 2][1] = r1;
            bh[np * 2 + 1][0] = r2; bh[np * 2 + 1][1] = r3;
            ldsm_x4(r0, r1, r2, r3, sBlo + boff);
            bl[np * 2][0] = r0; bl[np * 2][1] = r1;
            bl[np * 2 + 1][0] = r2; bl[np * 2 + 1][1] = r3;
        }
#pragma unroll
        for (int mt = 0; mt < 2; mt++)
#pragma unroll
            for (int nt = 0; nt < 4; nt++) {
                mma16816(acc[mt][nt], ah[mt], bh[nt]);
                mma16816(acc[mt][nt], ah[mt], bl[nt]);
                mma16816(acc[mt][nt], al[mt], bh[nt]);
            }
    }

    // ---- epilogue: bias + relu, split to bf16 hi/lo ----
#pragma unroll
    for (int mt = 0; mt < 2; mt++) {
#pragma unroll
        for (int nt = 0; nt < 4; nt++) {
            int gcol = bcol + wn + nt * 8 + (lane & 3) * 2;
            float b0 = bias[gcol], b1 = bias[gcol + 1];
#pragma unroll
            for (int hrow = 0; hrow < 2; hrow++) {
                int grow = brow + wm + mt * 16 + (lane >> 2) + hrow * 8;
                if (grow < M) {
                    float o0 = fmaxf(acc[mt][nt][hrow * 2 + 0] + b0, 0.f);
                    float o1 = fmaxf(acc[mt][nt][hrow * 2 + 1] + b1, 0.f);
                    __nv_bfloat16 h0 = __float2bfloat16_rn(o0);
                    __nv_bfloat16 h1 = __float2bfloat16_rn(o1);
                    __nv_bfloat16 l0 = __float2bfloat16_rn(o0 - __bfloat162float(h0));
                    __nv_bfloat16 l1 = __float2bfloat16_rn(o1 - __bfloat162float(h1));
                    __nv_bfloat162 hp(h0, h1), lp(l0, l1);
                    size_t o = (size_t)grow * 256 + gcol;
                    *(__nv_bfloat162*)(Hhi + o) = hp;
                    *(__nv_bfloat162*)(Hlo + o) = lp;
                }
            }
        }
    }
}

// ---------------- GEMM2: C = act(Hbf16 @ Wt2^T + b2), fp32 out --------------
// A: [M,256] bf16 hi/lo. Wt2: [128,256] bf16 hi/lo. Ntot=128, Ktot=256.
template <bool RELU>
__global__ void __launch_bounds__(256, 2)
gemm2_bfA(const __nv_bfloat16* __restrict__ Ahi, const __nv_bfloat16* __restrict__ Alo,
          const __nv_bfloat16* __restrict__ Bhi, const __nv_bfloat16* __restrict__ Blo,
          const float* __restrict__ bias, float* __restrict__ C, int M) {
    extern __shared__ char smem[];
    const uint32_t sb = smem_u32(smem);
    const uint32_t sAhi = sb;
    const uint32_t sAlo = sb + ATILE;
    const uint32_t sBhi = sb + 2 * ATILE;
    const uint32_t sBlo = sb + 2 * ATILE + BTILE;

    const int tid  = threadIdx.x;
    const int lane = tid & 31;
    const int wid  = tid >> 5;
    const int wm   = (wid & 1) * 32;
    const int wn   = (wid >> 1) * 32;
    const int brow = blockIdx.y * 64;
    const int bcol = 0;
    const int Ktot = 256;

    float acc[2][4][4];
#pragma unroll
    for (int i = 0; i < 2; i++)
#pragma unroll
        for (int j = 0; j < 4; j++)
#pragma unroll
            for (int k = 0; k < 4; k++) acc[i][j][k] = 0.f;

#pragma unroll
    for (int ch = 0; ch < 2; ch++) {
        const int kc = ch << 7;
        if (ch) __syncthreads();
        // A: 64 rows x 256B ; B: 128 rows x 256B
#pragma unroll
        for (int i = 0; i < 4; i++) {
            int id = tid + i * 256;            // 0..1023
            int row = id >> 4, off = (id & 15) * 16;
            uint32_t sdst = (uint32_t)(row * SROWB + off);
            int asz = (brow + row) < M ? 16 : 0;
            const char* ah = (const char*)(Ahi + (size_t)(brow + row) * Ktot + kc) + off;
            const char* al = (const char*)(Alo + (size_t)(brow + row) * Ktot + kc) + off;
            cp_async16(sAhi + sdst, ah, asz);
            cp_async16(sAlo + sdst, al, asz);
        }
#pragma unroll
        for (int i = 0; i < 8; i++) {
            int id = tid + i * 256;            // 0..2047
            int row = id >> 4, off = (id & 15) * 16;
            uint32_t sdst = (uint32_t)(row * SROWB + off);
            const char* bh = (const char*)(Bhi + (size_t)(bcol + row) * Ktot + kc) + off;
            const char* bl = (const char*)(Blo + (size_t)(bcol + row) * Ktot + kc) + off;
            cp_async16(sBhi + sdst, bh, 16);
            cp_async16(sBlo + sdst, bl, 16);
        }
        cp_commit();
        cp_wait0();
        __syncthreads();

#pragma unroll
        for (int kk = 0; kk < 8; kk++) {
            const uint32_t kb = (uint32_t)(kk * 32);
            uint32_t ah[2][4], al[2][4];
#pragma unroll
            for (int mt = 0; mt < 2; mt++) {
                uint32_t arow = (uint32_t)(wm + mt * 16 + (lane & 15));
                uint32_t aoff = arow * SROWB + kb + ((lane >> 4) << 4);
                ldsm_x4(ah[mt][0], ah[mt][1], ah[mt][2], ah[mt][3], sAhi + aoff);
                ldsm_x4(al[mt][0], al[mt][1], al[mt][2], al[mt][3], sAlo + aoff);
            }
            uint32_t bh[4][2], bl[4][2];
#pragma unroll
            for (int np = 0; np < 2; np++) {
                int g = lane >> 3, r = lane & 7;
                uint32_t browi = (uint32_t)(wn + np * 16 + ((g & 2) ? 8 : 0) + r);
                uint32_t boff = browi * SROWB + kb + ((g & 1) << 4);
                uint32_t r0, r1, r2, r3;
                ldsm_x4(r0, r1, r2, r3, sBhi + boff);
                bh[np * 2][0] = r0; bh[np * 2][1] = r1;
                bh[np * 2 + 1][0] = r2; bh[np * 2 + 1][1] = r3;
                ldsm_x4(r0, r1, r2, r3, sBlo + boff);
                bl[np * 2][0] = r0; bl[np * 2][1] = r1;
                bl[np * 2 + 1][0] = r2; bl[np * 2 + 1][1] = r3;
            }
#pragma unroll
            for (int mt = 0; mt < 2; mt++)
#pragma unroll
                for (int nt = 0; nt < 4; nt++) {
                    mma16816(acc[mt][nt], ah[mt], bh[nt]);
                    mma16816(acc[mt][nt], ah[mt], bl[nt]);
                    mma16816(acc[mt][nt], al[mt], bh[nt]);
                }
        }
    }

#pragma unroll
    for (int mt = 0; mt < 2; mt++) {
#pragma unroll
        for (int nt = 0; nt < 4; nt++) {
            int gcol = bcol + wn + nt * 8 + (lane & 3) * 2;
            float b0 = bias[gcol], b1 = bias[gcol + 1];
#pragma unroll
            for (int hrow = 0; hrow < 2; hrow++) {
                int grow = brow + wm + mt * 16 + (lane >> 2) + hrow * 8;
                if (grow < M) {
                    float o0 = acc[mt][nt][hrow * 2 + 0] + b0;
                    float o1 = acc[mt][nt][hrow * 2 + 1] + b1;
                    if (RELU) { o0 = fmaxf(o0, 0.f); o1 = fmaxf(o1, 0.f); }
                    *(float2*)(C + (size_t)grow * 128 + gcol) = make_float2(o0, o1);
                }
            }
        }
    }
}

// ---------------- launch ----------------
extern "C" void kernel_launch(void* const* d_in, const int* in_sizes, int n_in,
                              void* d_out, int out_size) {
    const float* x     = (const float*)d_in[0];
    const int*   ei    = (const int*)d_in[1];
    const int*   ea    = (const int*)d_in[2];
    const float* ee1_0 = (const float*)d_in[3];
    const float* ee2_0 = (const float*)d_in[4];
    const float* W1_0  = (const float*)d_in[5];
    const float* b1_0  = (const float*)d_in[6];
    const float* W2_0  = (const float*)d_in[7];
    const float* b2_0  = (const float*)d_in[8];
    const float* ee1_1 = (const float*)d_in[9];
    const float* ee2_1 = (const float*)d_in[10];
    const float* W1_1  = (const float*)d_in[11];
    const float* b1_1  = (const float*)d_in[12];
    const float* W2_1  = (const float*)d_in[13];
    const float* b2_1  = (const float*)d_in[14];
    float* out = (float*)d_out;

    const int N = in_sizes[0] / DD;  // 50000
    const int E = in_sizes[1] / 2;   // 800000

    float *aggr, *y0;
    __nv_bfloat16 *Hhi, *Hlo, *Wt;
    cudaGetSymbolAddress((void**)&aggr, g_aggr);
    cudaGetSymbolAddress((void**)&y0, g_y0);
    cudaGetSymbolAddress((void**)&Hhi, g_Hhi);
    cudaGetSymbolAddress((void**)&Hlo, g_Hlo);
    cudaGetSymbolAddress((void**)&Wt, g_Wt);

    cudaFuncSetAttribute(gemm1_f32A, cudaFuncAttributeMaxDynamicSharedMemorySize, GEMM_SMEM);
    cudaFuncSetAttribute(gemm2_bfA<true>, cudaFuncAttributeMaxDynamicSharedMemorySize, GEMM_SMEM);
    cudaFuncSetAttribute(gemm2_bfA<false>, cudaFuncAttributeMaxDynamicSharedMemorySize, GEMM_SMEM);

    const long n4_aggr = (long)N * DD / 4;
    dim3 zgrid((unsigned)((n4_aggr + 255) / 256));
    const long sc_threads = (long)E * 32;
    dim3 sgrid((unsigned)((sc_threads + 255) / 256));

    const int MT = (N + 63) / 64;    // 782
    dim3 g1grid(2, MT);              // Ntot = 256
    dim3 g2grid(1, MT);              // Ntot = 128

    // prep: zero aggr (layer 0) + all weight transposes, one launch
    prep_kernel<<<ZBLOCKS + 512, 256>>>((float4*)aggr, n4_aggr, W1_0, W2_0, W1_1, W2_1, Wt);

    // ============ layer 0 ============
    scatter_kernel<<<sgrid, 256>>>(x, ei, ea, ee1_0, ee2_0, aggr, E);
    gemm1_f32A<<<g1grid, 256, GEMM_SMEM>>>(aggr, Wt + 0 * 32768, Wt + 1 * 32768, b1_0, Hhi, Hlo, N);
    gemm2_bfA<true><<<g2grid, 256, GEMM_SMEM>>>(Hhi, Hlo, Wt + 2 * 32768, Wt + 3 * 32768, b2_0, y0, N);

    // ============ layer 1 ============
    zero_kernel<<<zgrid, 256>>>((float4*)aggr, n4_aggr);
    scatter_kernel<<<sgrid, 256>>>(y0, ei, ea, ee1_1, ee2_1, aggr, E);
    gemm1_f32A<<<g1grid, 256, GEMM_SMEM>>>(aggr, Wt + 4 * 32768, Wt + 5 * 32768, b1_1, Hhi, Hlo, N);
    gemm2_bfA<false><<<g2grid, 256, GEMM_SMEM>>>(Hhi, Hlo, Wt + 6 * 32768, Wt + 7 * 32768, b2_1, out, N);
}

// round 6
// speedup vs baseline: 1.7392x; 1.1051x over previous
#include <cuda_runtime.h>
#include <cuda_bf16.h>
#include <cstdint>

#define NN 50000
#define EE 800000
#define DD 128

// ---------------- scratch (static device globals) ----------------
__device__ float g_aggr[(size_t)NN * DD];                 // 25.6 MB
__device__ float g_y0[(size_t)NN * DD];                   // 25.6 MB
__device__ __nv_bfloat16 g_Hhi[(size_t)NN * 2 * DD];      // 25.6 MB
__device__ __nv_bfloat16 g_Hlo[(size_t)NN * 2 * DD];      // 25.6 MB
__device__ __nv_bfloat16 g_Wt[8][256 * 128];
// CSR
__device__ int g_deg[NN];
__device__ int g_off[NN + 1];
__device__ int g_cursor[NN];
__device__ uint32_t g_payload[EE];   // src | combo<<16

// ---------------- PTX helpers (base ISA only) ----------------
__device__ __forceinline__ uint32_t smem_u32(const void* p) {
    uint32_t a;
    asm("{ .reg .u64 t; cvta.to.shared.u64 t, %1; cvt.u32.u64 %0, t; }" : "=r"(a) : "l"(p));
    return a;
}
__device__ __forceinline__ void cp_async16(uint32_t dst, const void* src, int srcbytes) {
    asm volatile("cp.async.cg.shared.global [%0], [%1], 16, %2;"
                 :: "r"(dst), "l"(src), "r"(srcbytes) : "memory");
}
__device__ __forceinline__ void cp_commit() { asm volatile("cp.async.commit_group;" ::: "memory"); }
__device__ __forceinline__ void cp_wait0()  { asm volatile("cp.async.wait_group 0;" ::: "memory"); }

__device__ __forceinline__ void ldsm_x4(uint32_t& r0, uint32_t& r1, uint32_t& r2, uint32_t& r3,
                                        uint32_t addr) {
    asm volatile("ldmatrix.sync.aligned.m8n8.x4.shared.b16 {%0,%1,%2,%3}, [%4];"
                 : "=r"(r0), "=r"(r1), "=r"(r2), "=r"(r3) : "r"(addr));
}
__device__ __forceinline__ void mma16816(float* d, const uint32_t* a, const uint32_t* b) {
    asm volatile(
        "mma.sync.aligned.m16n8k16.row.col.f32.bf16.bf16.f32 "
        "{%0,%1,%2,%3}, {%4,%5,%6,%7}, {%8,%9}, {%0,%1,%2,%3};"
        : "+f"(d[0]), "+f"(d[1]), "+f"(d[2]), "+f"(d[3])
        : "r"(a[0]), "r"(a[1]), "r"(a[2]), "r"(a[3]), "r"(b[0]), "r"(b[1]));
}

// ---------------- prep: weight transposes + zero deg, one launch ------------
__global__ void __launch_bounds__(256)
prep_kernel(const float* __restrict__ W10, const float* __restrict__ W20,
            const float* __restrict__ W11, const float* __restrict__ W21,
            __nv_bfloat16* __restrict__ wt, int* __restrict__ deg) {
    int b = blockIdx.x;
    if (b >= 512) {  // zero deg: blocks 512..707
        int i = (b - 512) * 256 + threadIdx.x;
        if (i < NN) deg[i] = 0;
        return;
    }
    int which = b >> 7;
    int i = ((b & 127) << 8) + threadIdx.x;
    const float* W;
    int K, N;
    if (which == 0)      { W = W10; K = 128; N = 256; }
    else if (which == 1) { W = W20; K = 256; N = 128; }
    else if (which == 2) { W = W11; K = 128; N = 256; }
    else                 { W = W21; K = 256; N = 128; }
    int k = i / N, n = i % N;
    float a = W[i];
    __nv_bfloat16 h = __float2bfloat16_rn(a);
    __nv_bfloat16 l = __float2bfloat16_rn(a - __bfloat162float(h));
    __nv_bfloat16* thi = wt + (size_t)(2 * which) * 32768;
    __nv_bfloat16* tlo = thi + 32768;
    thi[n * K + k] = h;
    tlo[n * K + k] = l;
}

// ---------------- CSR build ----------------
__global__ void __launch_bounds__(256)
hist_kernel(const int* __restrict__ ei, int* __restrict__ deg, int E) {
    int e = blockIdx.x * 256 + threadIdx.x;
    if (e < E) atomicAdd(&deg[ei[E + e]], 1);
}

__global__ void __launch_bounds__(1024)
scan_kernel(const int* __restrict__ deg, int* __restrict__ off,
            int* __restrict__ cursor, int N, int E) {
    __shared__ int buf[1024];
    const int tid = threadIdx.x;
    const int per = (N + 1023) / 1024;
    int start = tid * per;
    int end = min(start + per, N);
    int s = 0;
    for (int i = start; i < end; i++) s += deg[i];
    buf[tid] = s;
    __syncthreads();
#pragma unroll
    for (int ofs = 1; ofs < 1024; ofs <<= 1) {
        int t = (tid >= ofs) ? buf[tid - ofs] : 0;
        __syncthreads();
        buf[tid] += t;
        __syncthreads();
    }
    int run = buf[tid] - s;  // exclusive base
    for (int i = start; i < end; i++) {
        off[i] = run;
        cursor[i] = run;
        run += deg[i];
    }
    if (tid == 1023) off[N] = E;
}

__global__ void __launch_bounds__(256)
fill_kernel(const int* __restrict__ ei, const int* __restrict__ ea,
            int* __restrict__ cursor, uint32_t* __restrict__ payload, int E) {
    int e = blockIdx.x * 256 + threadIdx.x;
    if (e >= E) return;
    int src = ei[e];
    int dst = ei[E + e];
    int a0 = ea[2 * e];
    int a1 = ea[2 * e + 1];
    int pos = atomicAdd(&cursor[dst], 1);
    payload[pos] = (uint32_t)src | ((uint32_t)(a0 * 3 + a1) << 16);
}

// ---------------- gather: aggr[n] = sum_{e in CSR[n]} x[src_e] + combo[c_e] ----
// one warp per node; 8 warps/block; 18-combo table in smem.
__global__ void __launch_bounds__(256)
gather_kernel(const float* __restrict__ x,
              const int* __restrict__ off, const uint32_t* __restrict__ payload,
              const float* __restrict__ ee1, const float* __restrict__ ee2,
              float* __restrict__ aggr, int N) {
    __shared__ float combo[18 * 128];
    const int tid = threadIdx.x;
#pragma unroll
    for (int k = 0; k < 9; k++) {
        int idx = tid + k * 256;
        int c = idx >> 7, d = idx & 127;
        combo[idx] = ee1[(c / 3) * 128 + d] + ee2[(c % 3) * 128 + d];
    }
    __syncthreads();

    const int lane = tid & 31;
    const int n = blockIdx.x * 8 + (tid >> 5);
    if (n >= N) return;
    const int d4 = lane * 4;

    int s = off[n];
    int e = off[n + 1];
    float4 acc = make_float4(0.f, 0.f, 0.f, 0.f);
    int i = s;
    for (; i + 1 < e; i += 2) {
        uint32_t p0 = payload[i];
        uint32_t p1 = payload[i + 1];
        float4 x0 = *(const float4*)(x + (size_t)(p0 & 0xFFFF) * 128 + d4);
        float4 c0 = *(const float4*)(combo + (p0 >> 16) * 128 + d4);
        float4 x1 = *(const float4*)(x + (size_t)(p1 & 0xFFFF) * 128 + d4);
        float4 c1 = *(const float4*)(combo + (p1 >> 16) * 128 + d4);
        acc.x += x0.x + c0.x + x1.x + c1.x;
        acc.y += x0.y + c0.y + x1.y + c1.y;
        acc.z += x0.z + c0.z + x1.z + c1.z;
        acc.w += x0.w + c0.w + x1.w + c1.w;
    }
    if (i < e) {
        uint32_t p0 = payload[i];
        float4 x0 = *(const float4*)(x + (size_t)(p0 & 0xFFFF) * 128 + d4);
        float4 c0 = *(const float4*)(combo + (p0 >> 16) * 128 + d4);
        acc.x += x0.x + c0.x;
        acc.y += x0.y + c0.y;
        acc.z += x0.z + c0.z;
        acc.w += x0.w + c0.w;
    }
    *(float4*)(aggr + (size_t)n * 128 + d4) = acc;
}

// ---------------- tiling constants: BM=64, BN=128, 2 CTAs/SM ----------------
#define SROWB 272
#define ATILE (64 * SROWB)
#define BTILE (128 * SROWB)
#define GEMM_SMEM (2 * ATILE + 2 * BTILE)  // 104448 B

// ---------------- GEMM1: H = relu(Afp32 @ Wt1^T + b1), H as bf16 hi/lo ------
__global__ void __launch_bounds__(256, 2)
gemm1_f32A(const float* __restrict__ A,
           const __nv_bfloat16* __restrict__ Bhi, const __nv_bfloat16* __restrict__ Blo,
           const float* __restrict__ bias,
           __nv_bfloat16* __restrict__ Hhi, __nv_bfloat16* __restrict__ Hlo,
           int M) {
    extern __shared__ char smem[];
    const uint32_t sb = smem_u32(smem);
    const uint32_t sAhi = sb;
    const uint32_t sAlo = sb + ATILE;
    const uint32_t sBhi = sb + 2 * ATILE;
    const uint32_t sBlo = sb + 2 * ATILE + BTILE;

    const int tid  = threadIdx.x;
    const int lane = tid & 31;
    const int wid  = tid >> 5;
    const int wm   = (wid & 1) * 32;
    const int wn   = (wid >> 1) * 32;
    const int brow = blockIdx.y * 64;
    const int bcol = blockIdx.x * 128;

#pragma unroll
    for (int i = 0; i < 8; i++) {
        int id = tid + i * 256;
        int row = id >> 4, off = (id & 15) * 16;
        uint32_t sdst = (uint32_t)(row * SROWB + off);
        const char* bh = (const char*)(Bhi + (size_t)(bcol + row) * 128) + off;
        const char* bl = (const char*)(Blo + (size_t)(bcol + row) * 128) + off;
        cp_async16(sBhi + sdst, bh, 16);
        cp_async16(sBlo + sdst, bl, 16);
    }
    cp_commit();

#pragma unroll
    for (int i = 0; i < 8; i++) {
        int id = tid + i * 256;
        int row = id >> 5, f4 = id & 31;
        float4 v = make_float4(0.f, 0.f, 0.f, 0.f);
        if (brow + row < M) v = *(const float4*)(A + (size_t)(brow + row) * 128 + f4 * 4);
        __nv_bfloat16 h0 = __float2bfloat16_rn(v.x), h1 = __float2bfloat16_rn(v.y);
        __nv_bfloat16 h2 = __float2bfloat16_rn(v.z), h3 = __float2bfloat16_rn(v.w);
        __nv_bfloat16 l0 = __float2bfloat16_rn(v.x - __bfloat162float(h0));
        __nv_bfloat16 l1 = __float2bfloat16_rn(v.y - __bfloat162float(h1));
        __nv_bfloat16 l2 = __float2bfloat16_rn(v.z - __bfloat162float(h2));
        __nv_bfloat16 l3 = __float2bfloat16_rn(v.w - __bfloat162float(h3));
        __nv_bfloat162 hp0(h0, h1), hp1(h2, h3), lp0(l0, l1), lp1(l2, l3);
        uint2 hv = make_uint2(*(uint32_t*)&hp0, *(uint32_t*)&hp1);
        uint2 lv = make_uint2(*(uint32_t*)&lp0, *(uint32_t*)&lp1);
        uint32_t sdst = (uint32_t)(row * SROWB + f4 * 8);
        *(uint2*)(smem + sdst) = hv;
        *(uint2*)(smem + ATILE + sdst) = lv;
    }
    cp_wait0();
    __syncthreads();

    float acc[2][4][4];
#pragma unroll
    for (int i = 0; i < 2; i++)
#pragma unroll
        for (int j = 0; j < 4; j++)
#pragma unroll
            for (int k = 0; k < 4; k++) acc[i][j][k] = 0.f;

#pragma unroll
    for (int kk = 0; kk < 8; kk++) {
        const uint32_t kb = (uint32_t)(kk * 32);
        uint32_t ah[2][4], al[2][4];
#pragma unroll
        for (int mt = 0; mt < 2; mt++) {
            uint32_t arow = (uint32_t)(wm + mt * 16 + (lane & 15));
            uint32_t aoff = arow * SROWB + kb + ((lane >> 4) << 4);
            ldsm_x4(ah[mt][0], ah[mt][1], ah[mt][2], ah[mt][3], sAhi + aoff);
            ldsm_x4(al[mt][0], al[mt][1], al[mt][2], al[mt][3], sAlo + aoff);
        }
        uint32_t bh[4][2], bl[4][2];
#pragma unroll
        for (int np = 0; np < 2; np++) {
            int g = lane >> 3, r = lane & 7;
            uint32_t browi = (uint32_t)(wn + np * 16 + ((g & 2) ? 8 : 0) + r);
            uint32_t boff = browi * SROWB + kb + ((g & 1) << 4);
            uint32_t r0, r1, r2, r3;
            ldsm_x4(r0, r1, r2, r3, sBhi + boff);
            bh[np * 2][0] = r0; bh[np * 2][1] = r1;
            bh[np * 2 + 1][0] = r2; bh[np * 2 + 1][1] = r3;
            ldsm_x4(r0, r1, r2, r3, sBlo + boff);
            bl[np * 2][0] = r0; bl[np * 2][1] = r1;
            bl[np * 2 + 1][0] = r2; bl[np * 2 + 1][1] = r3;
        }
#pragma unroll
        for (int mt = 0; mt < 2; mt++)
#pragma unroll
            for (int nt = 0; nt < 4; nt++) {
                mma16816(acc[mt][nt], ah[mt], bh[nt]);
                mma16816(acc[mt][nt], ah[mt], bl[nt]);
                mma16816(acc[mt][nt], al[mt], bh[nt]);
            }
    }

#pragma unroll
    for (int mt = 0; mt < 2; mt++) {
#pragma unroll
        for (int nt = 0; nt < 4; nt++) {
            int gcol = bcol + wn + nt * 8 + (lane & 3) * 2;
            float b0 = bias[gcol], b1 = bias[gcol + 1];
#pragma unroll
            for (int hrow = 0; hrow < 2; hrow++) {
                int grow = brow + wm + mt * 16 + (lane >> 2) + hrow * 8;
                if (grow < M) {
                    float o0 = fmaxf(acc[mt][nt][hrow * 2 + 0] + b0, 0.f);
                    float o1 = fmaxf(acc[mt][nt][hrow * 2 + 1] + b1, 0.f);
                    __nv_bfloat16 h0 = __float2bfloat16_rn(o0);
                    __nv_bfloat16 h1 = __float2bfloat16_rn(o1);
                    __nv_bfloat16 l0 = __float2bfloat16_rn(o0 - __bfloat162float(h0));
                    __nv_bfloat16 l1 = __float2bfloat16_rn(o1 - __bfloat162float(h1));
                    __nv_bfloat162 hp(h0, h1), lp(l0, l1);
                    size_t o = (size_t)grow * 256 + gcol;
                    *(__nv_bfloat162*)(Hhi + o) = hp;
                    *(__nv_bfloat162*)(Hlo + o) = lp;
                }
            }
        }
    }
}

// ---------------- GEMM2: C = act(Hbf16 @ Wt2^T + b2), fp32 out --------------
template <bool RELU>
__global__ void __launch_bounds__(256, 2)
gemm2_bfA(const __nv_bfloat16* __restrict__ Ahi, const __nv_bfloat16* __restrict__ Alo,
          const __nv_bfloat16* __restrict__ Bhi, const __nv_bfloat16* __restrict__ Blo,
          const float* __restrict__ bias, float* __restrict__ C, int M) {
    extern __shared__ char smem[];
    const uint32_t sb = smem_u32(smem);
    const uint32_t sAhi = sb;
    const uint32_t sAlo = sb + ATILE;
    const uint32_t sBhi = sb + 2 * ATILE;
    const uint32_t sBlo = sb + 2 * ATILE + BTILE;

    const int tid  = threadIdx.x;
    const int lane = tid & 31;
    const int wid  = tid >> 5;
    const int wm   = (wid & 1) * 32;
    const int wn   = (wid >> 1) * 32;
    const int brow = blockIdx.y * 64;
    const int Ktot = 256;

    float acc[2][4][4];
#pragma unroll
    for (int i = 0; i < 2; i++)
#pragma unroll
        for (int j = 0; j < 4; j++)
#pragma unroll
            for (int k = 0; k < 4; k++) acc[i][j][k] = 0.f;

#pragma unroll
    for (int ch = 0; ch < 2; ch++) {
        const int kc = ch << 7;
        if (ch) __syncthreads();
#pragma unroll
        for (int i = 0; i < 4; i++) {
            int id = tid + i * 256;
            int row = id >> 4, off = (id & 15) * 16;
            uint32_t sdst = (uint32_t)(row * SROWB + off);
            int asz = (brow + row) < M ? 16 : 0;
            const char* ah = (const char*)(Ahi + (size_t)(brow + row) * Ktot + kc) + off;
            const char* al = (const char*)(Alo + (size_t)(brow + row) * Ktot + kc) + off;
            cp_async16(sAhi + sdst, ah, asz);
            cp_async16(sAlo + sdst, al, asz);
        }
#pragma unroll
        for (int i = 0; i < 8; i++) {
            int id = tid + i * 256;
            int row = id >> 4, off = (id & 15) * 16;
            uint32_t sdst = (uint32_t)(row * SROWB + off);
            const char* bh = (const char*)(Bhi + (size_t)row * Ktot + kc) + off;
            const char* bl = (const char*)(Blo + (size_t)row * Ktot + kc) + off;
            cp_async16(sBhi + sdst, bh, 16);
            cp_async16(sBlo + sdst, bl, 16);
        }
        cp_commit();
        cp_wait0();
        __syncthreads();

#pragma unroll
        for (int kk = 0; kk < 8; kk++) {
            const uint32_t kb = (uint32_t)(kk * 32);
            uint32_t ah[2][4], al[2][4];
#pragma unroll
            for (int mt = 0; mt < 2; mt++) {
                uint32_t arow = (uint32_t)(wm + mt * 16 + (lane & 15));
                uint32_t aoff = arow * SROWB + kb + ((lane >> 4) << 4);
                ldsm_x4(ah[mt][0], ah[mt][1], ah[mt][2], ah[mt][3], sAhi + aoff);
                ldsm_x4(al[mt][0], al[mt][1], al[mt][2], al[mt][3], sAlo + aoff);
            }
            uint32_t bh[4][2], bl[4][2];
#pragma unroll
            for (int np = 0; np < 2; np++) {
                int g = lane >> 3, r = lane & 7;
                uint32_t browi = (uint32_t)(wn + np * 16 + ((g & 2) ? 8 : 0) + r);
                uint32_t boff = browi * SROWB + kb + ((g & 1) << 4);
                uint32_t r0, r1, r2, r3;
                ldsm_x4(r0, r1, r2, r3, sBhi + boff);
                bh[np * 2][0] = r0; bh[np * 2][1] = r1;
                bh[np * 2 + 1][0] = r2; bh[np * 2 + 1][1] = r3;
                ldsm_x4(r0, r1, r2, r3, sBlo + boff);
                bl[np * 2][0] = r0; bl[np * 2][1] = r1;
                bl[np * 2 + 1][0] = r2; bl[np * 2 + 1][1] = r3;
            }
#pragma unroll
            for (int mt = 0; mt < 2; mt++)
#pragma unroll
                for (int nt = 0; nt < 4; nt++) {
                    mma16816(acc[mt][nt], ah[mt], bh[nt]);
                    mma16816(acc[mt][nt], ah[mt], bl[nt]);
                    mma16816(acc[mt][nt], al[mt], bh[nt]);
                }
        }
    }

#pragma unroll
    for (int mt = 0; mt < 2; mt++) {
#pragma unroll
        for (int nt = 0; nt < 4; nt++) {
            int gcol = wn + nt * 8 + (lane & 3) * 2;
            float b0 = bias[gcol], b1 = bias[gcol + 1];
#pragma unroll
            for (int hrow = 0; hrow < 2; hrow++) {
                int grow = brow + wm + mt * 16 + (lane >> 2) + hrow * 8;
                if (grow < M) {
                    float o0 = acc[mt][nt][hrow * 2 + 0] + b0;
                    float o1 = acc[mt][nt][hrow * 2 + 1] + b1;
                    if (RELU) { o0 = fmaxf(o0, 0.f); o1 = fmaxf(o1, 0.f); }
                    *(float2*)(C + (size_t)grow * 128 + gcol) = make_float2(o0, o1);
                }
            }
        }
    }
}

// ---------------- launch ----------------
extern "C" void kernel_launch(void* const* d_in, const int* in_sizes, int n_in,
                              void* d_out, int out_size) {
    const float* x     = (const float*)d_in[0];
    const int*   ei    = (const int*)d_in[1];
    const int*   ea    = (const int*)d_in[2];
    const float* ee1_0 = (const float*)d_in[3];
    const float* ee2_0 = (const float*)d_in[4];
    const float* W1_0  = (const float*)d_in[5];
    const float* b1_0  = (const float*)d_in[6];
    const float* W2_0  = (const float*)d_in[7];
    const float* b2_0  = (const float*)d_in[8];
    const float* ee1_1 = (const float*)d_in[9];
    const float* ee2_1 = (const float*)d_in[10];
    const float* W1_1  = (const float*)d_in[11];
    const float* b1_1  = (const float*)d_in[12];
    const float* W2_1  = (const float*)d_in[13];
    const float* b2_1  = (const float*)d_in[14];
    float* out = (float*)d_out;

    const int N = in_sizes[0] / DD;  // 50000
    const int E = in_sizes[1] / 2;   // 800000

    float *aggr, *y0;
    __nv_bfloat16 *Hhi, *Hlo, *Wt;
    int *deg, *off, *cursor;
    uint32_t* payload;
    cudaGetSymbolAddress((void**)&aggr, g_aggr);
    cudaGetSymbolAddress((void**)&y0, g_y0);
    cudaGetSymbolAddress((void**)&Hhi, g_Hhi);
    cudaGetSymbolAddress((void**)&Hlo, g_Hlo);
    cudaGetSymbolAddress((void**)&Wt, g_Wt);
    cudaGetSymbolAddress((void**)&deg, g_deg);
    cudaGetSymbolAddress((void**)&off, g_off);
    cudaGetSymbolAddress((void**)&cursor, g_cursor);
    cudaGetSymbolAddress((void**)&payload, g_payload);

    cudaFuncSetAttribute(gemm1_f32A, cudaFuncAttributeMaxDynamicSharedMemorySize, GEMM_SMEM);
    cudaFuncSetAttribute(gemm2_bfA<true>, cudaFuncAttributeMaxDynamicSharedMemorySize, GEMM_SMEM);
    cudaFuncSetAttribute(gemm2_bfA<false>, cudaFuncAttributeMaxDynamicSharedMemorySize, GEMM_SMEM);

    const int MT = (N + 63) / 64;    // 782
    dim3 g1grid(2, MT);
    dim3 g2grid(1, MT);
    const int ggrid = (N + 7) / 8;   // gather: 8 nodes per block

    // ---- CSR build (edge structure shared by both layers) ----
    prep_kernel<<<512 + (NN + 255) / 256, 256>>>(W1_0, W2_0, W1_1, W2_1, Wt, deg);
    hist_kernel<<<(E + 255) / 256, 256>>>(ei, deg, E);
    scan_kernel<<<1, 1024>>>(deg, off, cursor, N, E);
    fill_kernel<<<(E + 255) / 256, 256>>>(ei, ea, cursor, payload, E);

    // ============ layer 0 ============
    gather_kernel<<<ggrid, 256>>>(x, off, payload, ee1_0, ee2_0, aggr, N);
    gemm1_f32A<<<g1grid, 256, GEMM_SMEM>>>(aggr, Wt + 0 * 32768, Wt + 1 * 32768, b1_0, Hhi, Hlo, N);
    gemm2_bfA<true><<<g2grid, 256, GEMM_SMEM>>>(Hhi, Hlo, Wt + 2 * 32768, Wt + 3 * 32768, b2_0, y0, N);

    // ============ layer 1 ============
    gather_kernel<<<ggrid, 256>>>(y0, off, payload, ee1_1, ee2_1, aggr, N);
    gemm1_f32A<<<g1grid, 256, GEMM_SMEM>>>(aggr, Wt + 4 * 32768, Wt + 5 * 32768, b1_1, Hhi, Hlo, N);
    gemm2_bfA<false><<<g2grid, 256, GEMM_SMEM>>>(Hhi, Hlo, Wt + 6 * 32768, Wt + 7 * 32768, b2_1, out, N);
}

// round 7
// speedup vs baseline: 2.3568x; 1.3552x over previous
#include <cuda_runtime.h>
#include <cuda_bf16.h>
#include <cstdint>

#define NN 50000
#define EE 800000
#define DD 128
#define BUCKET 64

// ---------------- scratch (static device globals) ----------------
__device__ float g_y0[(size_t)NN * DD];                   // 25.6 MB
__device__ __nv_bfloat16 g_Ahi[(size_t)NN * DD];          // 12.8 MB
__device__ __nv_bfloat16 g_Alo[(size_t)NN * DD];          // 12.8 MB
__device__ __nv_bfloat16 g_Hhi[(size_t)NN * 2 * DD];      // 25.6 MB
__device__ __nv_bfloat16 g_Hlo[(size_t)NN * 2 * DD];      // 25.6 MB
__device__ __nv_bfloat16 g_Wt[8][256 * 128];
__device__ int g_cnt[NN];
__device__ uint32_t g_payload[(size_t)NN * BUCKET];       // 12.8 MB

// ---------------- PTX helpers (base ISA only) ----------------
__device__ __forceinline__ uint32_t smem_u32(const void* p) {
    uint32_t a;
    asm("{ .reg .u64 t; cvta.to.shared.u64 t, %1; cvt.u32.u64 %0, t; }" : "=r"(a) : "l"(p));
    return a;
}
__device__ __forceinline__ void cp_async16(uint32_t dst, const void* src, int srcbytes) {
    asm volatile("cp.async.cg.shared.global [%0], [%1], 16, %2;"
                 :: "r"(dst), "l"(src), "r"(srcbytes) : "memory");
}
__device__ __forceinline__ void cp_commit() { asm volatile("cp.async.commit_group;" ::: "memory"); }
__device__ __forceinline__ void cp_wait0()  { asm volatile("cp.async.wait_group 0;" ::: "memory"); }

__device__ __forceinline__ void ldsm_x4(uint32_t& r0, uint32_t& r1, uint32_t& r2, uint32_t& r3,
                                        uint32_t addr) {
    asm volatile("ldmatrix.sync.aligned.m8n8.x4.shared.b16 {%0,%1,%2,%3}, [%4];"
                 : "=r"(r0), "=r"(r1), "=r"(r2), "=r"(r3) : "r"(addr));
}
__device__ __forceinline__ void mma16816(float* d, const uint32_t* a, const uint32_t* b) {
    asm volatile(
        "mma.sync.aligned.m16n8k16.row.col.f32.bf16.bf16.f32 "
        "{%0,%1,%2,%3}, {%4,%5,%6,%7}, {%8,%9}, {%0,%1,%2,%3};"
        : "+f"(d[0]), "+f"(d[1]), "+f"(d[2]), "+f"(d[3])
        : "r"(a[0]), "r"(a[1]), "r"(a[2]), "r"(a[3]), "r"(b[0]), "r"(b[1]));
}

// ---------------- prep: weight transposes + zero cnt ----------------
__global__ void __launch_bounds__(256)
prep_kernel(const float* __restrict__ W10, const float* __restrict__ W20,
            const float* __restrict__ W11, const float* __restrict__ W21,
            __nv_bfloat16* __restrict__ wt, int* __restrict__ cnt) {
    int b = blockIdx.x;
    if (b >= 512) {
        int i = (b - 512) * 256 + threadIdx.x;
        if (i < NN) cnt[i] = 0;
        return;
    }
    int which = b >> 7;
    int i = ((b & 127) << 8) + threadIdx.x;
    const float* W;
    int K, N;
    if (which == 0)      { W = W10; K = 128; N = 256; }
    else if (which == 1) { W = W20; K = 256; N = 128; }
    else if (which == 2) { W = W11; K = 128; N = 256; }
    else                 { W = W21; K = 256; N = 128; }
    int k = i / N, n = i % N;
    float a = W[i];
    __nv_bfloat16 h = __float2bfloat16_rn(a);
    __nv_bfloat16 l = __float2bfloat16_rn(a - __bfloat162float(h));
    __nv_bfloat16* thi = wt + (size_t)(2 * which) * 32768;
    __nv_bfloat16* tlo = thi + 32768;
    thi[n * K + k] = h;
    tlo[n * K + k] = l;
}

// ---------------- bucket fill ----------------
__global__ void __launch_bounds__(256)
fill_kernel(const int* __restrict__ ei, const int* __restrict__ ea,
            int* __restrict__ cnt, uint32_t* __restrict__ payload, int E) {
    int e = blockIdx.x * 256 + threadIdx.x;
    if (e >= E) return;
    int src = ei[e];
    int dst = ei[E + e];
    int a0 = ea[2 * e];
    int a1 = ea[2 * e + 1];
    int pos = atomicAdd(&cnt[dst], 1);
    payload[((size_t)dst << 6) + pos] = (uint32_t)src | ((uint32_t)(a0 * 3 + a1) << 16);
}

// ---------------- gather -> bf16 hi/lo ----------------
// one warp per node; unroll-4 edge loop; 18-combo table in smem.
__global__ void __launch_bounds__(256)
gather_kernel(const float* __restrict__ x,
              const int* __restrict__ cnt, const uint32_t* __restrict__ payload,
              const float* __restrict__ ee1, const float* __restrict__ ee2,
              __nv_bfloat16* __restrict__ Ahi, __nv_bfloat16* __restrict__ Alo,
              int N) {
    __shared__ float combo[18 * 128];
    const int tid = threadIdx.x;
#pragma unroll
    for (int k = 0; k < 9; k++) {
        int idx = tid + k * 256;
        int c = idx >> 7, d = idx & 127;
        combo[idx] = ee1[(c / 3) * 128 + d] + ee2[(c % 3) * 128 + d];
    }
    __syncthreads();

    const int lane = tid & 31;
    const int n = blockIdx.x * 8 + (tid >> 5);
    if (n >= N) return;
    const int d4 = lane * 4;

    const uint32_t* pl = payload + ((size_t)n << 6);
    int deg = cnt[n];
    float4 acc = make_float4(0.f, 0.f, 0.f, 0.f);
    int i = 0;
    for (; i + 3 < deg; i += 4) {
        uint32_t p0 = pl[i], p1 = pl[i + 1], p2 = pl[i + 2], p3 = pl[i + 3];
        float4 x0 = *(const float4*)(x + (size_t)(p0 & 0xFFFF) * 128 + d4);
        float4 x1 = *(const float4*)(x + (size_t)(p1 & 0xFFFF) * 128 + d4);
        float4 x2 = *(const float4*)(x + (size_t)(p2 & 0xFFFF) * 128 + d4);
        float4 x3 = *(const float4*)(x + (size_t)(p3 & 0xFFFF) * 128 + d4);
        float4 c0 = *(const float4*)(combo + (p0 >> 16) * 128 + d4);
        float4 c1 = *(const float4*)(combo + (p1 >> 16) * 128 + d4);
        float4 c2 = *(const float4*)(combo + (p2 >> 16) * 128 + d4);
        float4 c3 = *(const float4*)(combo + (p3 >> 16) * 128 + d4);
        acc.x += (x0.x + c0.x) + (x1.x + c1.x) + (x2.x + c2.x) + (x3.x + c3.x);
        acc.y += (x0.y + c0.y) + (x1.y + c1.y) + (x2.y + c2.y) + (x3.y + c3.y);
        acc.z += (x0.z + c0.z) + (x1.z + c1.z) + (x2.z + c2.z) + (x3.z + c3.z);
        acc.w += (x0.w + c0.w) + (x1.w + c1.w) + (x2.w + c2.w) + (x3.w + c3.w);
    }
    for (; i < deg; i++) {
        uint32_t p0 = pl[i];
        float4 x0 = *(const float4*)(x + (size_t)(p0 & 0xFFFF) * 128 + d4);
        float4 c0 = *(const float4*)(combo + (p0 >> 16) * 128 + d4);
        acc.x += x0.x + c0.x;
        acc.y += x0.y + c0.y;
        acc.z += x0.z + c0.z;
        acc.w += x0.w + c0.w;
    }

    __nv_bfloat16 h0 = __float2bfloat16_rn(acc.x), h1 = __float2bfloat16_rn(acc.y);
    __nv_bfloat16 h2 = __float2bfloat16_rn(acc.z), h3 = __float2bfloat16_rn(acc.w);
    __nv_bfloat16 l0 = __float2bfloat16_rn(acc.x - __bfloat162float(h0));
    __nv_bfloat16 l1 = __float2bfloat16_rn(acc.y - __bfloat162float(h1));
    __nv_bfloat16 l2 = __float2bfloat16_rn(acc.z - __bfloat162float(h2));
    __nv_bfloat16 l3 = __float2bfloat16_rn(acc.w - __bfloat162float(h3));
    __nv_bfloat162 hp0(h0, h1), hp1(h2, h3), lp0(l0, l1), lp1(l2, l3);
    size_t o = (size_t)n * 128 + d4;
    *(uint2*)(Ahi + o) = make_uint2(*(uint32_t*)&hp0, *(uint32_t*)&hp1);
    *(uint2*)(Alo + o) = make_uint2(*(uint32_t*)&lp0, *(uint32_t*)&lp1);
}

// ---------------- tiling constants: BM=64, BN=128, 2 CTAs/SM ----------------
#define SROWB 272
#define ATILE (64 * SROWB)
#define BTILE (128 * SROWB)
#define GEMM_SMEM (2 * ATILE + 2 * BTILE)  // 104448 B

// ---------------- GEMM1: H = relu(Abf16 @ Wt1^T + b1), H as bf16 hi/lo ------
// A: [M,128] bf16 hi/lo. Wt1: [256,128] bf16 hi/lo. Ntot=256, Ktot=128.
__global__ void __launch_bounds__(256, 2)
gemm1_bfA(const __nv_bfloat16* __restrict__ Ahi, const __nv_bfloat16* __restrict__ Alo,
          const __nv_bfloat16* __restrict__ Bhi, const __nv_bfloat16* __restrict__ Blo,
          const float* __restrict__ bias,
          __nv_bfloat16* __restrict__ Hhi, __nv_bfloat16* __restrict__ Hlo,
          int M) {
    extern __shared__ char smem[];
    const uint32_t sb = smem_u32(smem);
    const uint32_t sAhi = sb;
    const uint32_t sAlo = sb + ATILE;
    const uint32_t sBhi = sb + 2 * ATILE;
    const uint32_t sBlo = sb + 2 * ATILE + BTILE;

    const int tid  = threadIdx.x;
    const int lane = tid & 31;
    const int wid  = tid >> 5;
    const int wm   = (wid & 1) * 32;
    const int wn   = (wid >> 1) * 32;
    const int brow = blockIdx.y * 64;
    const int bcol = blockIdx.x * 128;

    // A: 64 rows x 256B
#pragma unroll
    for (int i = 0; i < 4; i++) {
        int id = tid + i * 256;
        int row = id >> 4, off = (id & 15) * 16;
        uint32_t sdst = (uint32_t)(row * SROWB + off);
        int asz = (brow + row) < M ? 16 : 0;
        const char* ah = (const char*)(Ahi + (size_t)(brow + row) * 128) + off;
        const char* al = (const char*)(Alo + (size_t)(brow + row) * 128) + off;
        cp_async16(sAhi + sdst, ah, asz);
        cp_async16(sAlo + sdst, al, asz);
    }
    // B: 128 rows x 256B
#pragma unroll
    for (int i = 0; i < 8; i++) {
        int id = tid + i * 256;
        int row = id >> 4, off = (id & 15) * 16;
        uint32_t sdst = (uint32_t)(row * SROWB + off);
        const char* bh = (const char*)(Bhi + (size_t)(bcol + row) * 128) + off;
        const char* bl = (const char*)(Blo + (size_t)(bcol + row) * 128) + off;
        cp_async16(sBhi + sdst, bh, 16);
        cp_async16(sBlo + sdst, bl, 16);
    }
    cp_commit();
    cp_wait0();
    __syncthreads();

    float acc[2][4][4];
#pragma unroll
    for (int i = 0; i < 2; i++)
#pragma unroll
        for (int j = 0; j < 4; j++)
#pragma unroll
            for (int k = 0; k < 4; k++) acc[i][j][k] = 0.f;

#pragma unroll
    for (int kk = 0; kk < 8; kk++) {
        const uint32_t kb = (uint32_t)(kk * 32);
        uint32_t ah[2][4], al[2][4];
#pragma unroll
        for (int mt = 0; mt < 2; mt++) {
            uint32_t arow = (uint32_t)(wm + mt * 16 + (lane & 15));
            uint32_t aoff = arow * SROWB + kb + ((lane >> 4) << 4);
            ldsm_x4(ah[mt][0], ah[mt][1], ah[mt][2], ah[mt][3], sAhi + aoff);
            ldsm_x4(al[mt][0], al[mt][1], al[mt][2], al[mt][3], sAlo + aoff);
        }
        uint32_t bh[4][2], bl[4][2];
#pragma unroll
        for (int np = 0; np < 2; np++) {
            int g = lane >> 3, r = lane & 7;
            uint32_t browi = (uint32_t)(wn + np * 16 + ((g & 2) ? 8 : 0) + r);
            uint32_t boff = browi * SROWB + kb + ((g & 1) << 4);
            uint32_t r0, r1, r2, r3;
            ldsm_x4(r0, r1, r2, r3, sBhi + boff);
            bh[np * 2][0] = r0; bh[np * 2][1] = r1;
            bh[np * 2 + 1][0] = r2; bh[np * 2 + 1][1] = r3;
            ldsm_x4(r0, r1, r2, r3, sBlo + boff);
            bl[np * 2][0] = r0; bl[np * 2][1] = r1;
            bl[np * 2 + 1][0] = r2; bl[np * 2 + 1][1] = r3;
        }
#pragma unroll
        for (int mt = 0; mt < 2; mt++)
#pragma unroll
            for (int nt = 0; nt < 4; nt++) {
                mma16816(acc[mt][nt], ah[mt], bh[nt]);
                mma16816(acc[mt][nt], ah[mt], bl[nt]);
                mma16816(acc[mt][nt], al[mt], bh[nt]);
            }
    }

#pragma unroll
    for (int mt = 0; mt < 2; mt++) {
#pragma unroll
        for (int nt = 0; nt < 4; nt++) {
            int gcol = bcol + wn + nt * 8 + (lane & 3) * 2;
            float b0 = bias[gcol], b1 = bias[gcol + 1];
#pragma unroll
            for (int hrow = 0; hrow < 2; hrow++) {
                int grow = brow + wm + mt * 16 + (lane >> 2) + hrow * 8;
                if (grow < M) {
                    float o0 = fmaxf(acc[mt][nt][hrow * 2 + 0] + b0, 0.f);
                    float o1 = fmaxf(acc[mt][nt][hrow * 2 + 1] + b1, 0.f);
                    __nv_bfloat16 h0 = __float2bfloat16_rn(o0);
                    __nv_bfloat16 h1 = __float2bfloat16_rn(o1);
                    __nv_bfloat16 l0 = __float2bfloat16_rn(o0 - __bfloat162float(h0));
                    __nv_bfloat16 l1 = __float2bfloat16_rn(o1 - __bfloat162float(h1));
                    __nv_bfloat162 hp(h0, h1), lp(l0, l1);
                    size_t o = (size_t)grow * 256 + gcol;
                    *(__nv_bfloat162*)(Hhi + o) = hp;
                    *(__nv_bfloat162*)(Hlo + o) = lp;
                }
            }
        }
    }
}

// ---------------- GEMM2: C = act(Hbf16 @ Wt2^T + b2), fp32 out --------------
template <bool RELU>
__global__ void __launch_bounds__(256, 2)
gemm2_bfA(const __nv_bfloat16* __restrict__ Ahi, const __nv_bfloat16* __restrict__ Alo,
          const __nv_bfloat16* __restrict__ Bhi, const __nv_bfloat16* __restrict__ Blo,
          const float* __restrict__ bias, float* __restrict__ C, int M) {
    extern __shared__ char smem[];
    const uint32_t sb = smem_u32(smem);
    const uint32_t sAhi = sb;
    const uint32_t sAlo = sb + ATILE;
    const uint32_t sBhi = sb + 2 * ATILE;
    const uint32_t sBlo = sb + 2 * ATILE + BTILE;

    const int tid  = threadIdx.x;
    const int lane = tid & 31;
    const int wid  = tid >> 5;
    const int wm   = (wid & 1) * 32;
    const int wn   = (wid >> 1) * 32;
    const int brow = blockIdx.y * 64;
    const int Ktot = 256;

    float acc[2][4][4];
#pragma unroll
    for (int i = 0; i < 2; i++)
#pragma unroll
        for (int j = 0; j < 4; j++)
#pragma unroll
            for (int k = 0; k < 4; k++) acc[i][j][k] = 0.f;

#pragma unroll
    for (int ch = 0; ch < 2; ch++) {
        const int kc = ch << 7;
        if (ch) __syncthreads();
#pragma unroll
        for (int i = 0; i < 4; i++) {
            int id = tid + i * 256;
            int row = id >> 4, off = (id & 15) * 16;
            uint32_t sdst = (uint32_t)(row * SROWB + off);
            int asz = (brow + row) < M ? 16 : 0;
            const char* ah = (const char*)(Ahi + (size_t)(brow + row) * Ktot + kc) + off;
            const char* al = (const char*)(Alo + (size_t)(brow + row) * Ktot + kc) + off;
            cp_async16(sAhi + sdst, ah, asz);
            cp_async16(sAlo + sdst, al, asz);
        }
#pragma unroll
        for (int i = 0; i < 8; i++) {
            int id = tid + i * 256;
            int row = id >> 4, off = (id & 15) * 16;
            uint32_t sdst = (uint32_t)(row * SROWB + off);
            const char* bh = (const char*)(Bhi + (size_t)row * Ktot + kc) + off;
            const char* bl = (const char*)(Blo + (size_t)row * Ktot + kc) + off;
            cp_async16(sBhi + sdst, bh, 16);
            cp_async16(sBlo + sdst, bl, 16);
        }
        cp_commit();
        cp_wait0();
        __syncthreads();

#pragma unroll
        for (int kk = 0; kk < 8; kk++) {
            const uint32_t kb = (uint32_t)(kk * 32);
            uint32_t ah[2][4], al[2][4];
#pragma unroll
            for (int mt = 0; mt < 2; mt++) {
                uint32_t arow = (uint32_t)(wm + mt * 16 + (lane & 15));
                uint32_t aoff = arow * SROWB + kb + ((lane >> 4) << 4);
                ldsm_x4(ah[mt][0], ah[mt][1], ah[mt][2], ah[mt][3], sAhi + aoff);
                ldsm_x4(al[mt][0], al[mt][1], al[mt][2], al[mt][3], sAlo + aoff);
            }
            uint32_t bh[4][2], bl[4][2];
#pragma unroll
            for (int np = 0; np < 2; np++) {
                int g = lane >> 3, r = lane & 7;
                uint32_t browi = (uint32_t)(wn + np * 16 + ((g & 2) ? 8 : 0) + r);
                uint32_t boff = browi * SROWB + kb + ((g & 1) << 4);
                uint32_t r0, r1, r2, r3;
                ldsm_x4(r0, r1, r2, r3, sBhi + boff);
                bh[np * 2][0] = r0; bh[np * 2][1] = r1;
                bh[np * 2 + 1][0] = r2; bh[np * 2 + 1][1] = r3;
                ldsm_x4(r0, r1, r2, r3, sBlo + boff);
                bl[np * 2][0] = r0; bl[np * 2][1] = r1;
                bl[np * 2 + 1][0] = r2; bl[np * 2 + 1][1] = r3;
            }
#pragma unroll
            for (int mt = 0; mt < 2; mt++)
#pragma unroll
                for (int nt = 0; nt < 4; nt++) {
                    mma16816(acc[mt][nt], ah[mt], bh[nt]);
                    mma16816(acc[mt][nt], ah[mt], bl[nt]);
                    mma16816(acc[mt][nt], al[mt], bh[nt]);
                }
        }
    }

#pragma unroll
    for (int mt = 0; mt < 2; mt++) {
#pragma unroll
        for (int nt = 0; nt < 4; nt++) {
            int gcol = wn + nt * 8 + (lane & 3) * 2;
            float b0 = bias[gcol], b1 = bias[gcol + 1];
#pragma unroll
            for (int hrow = 0; hrow < 2; hrow++) {
                int grow = brow + wm + mt * 16 + (lane >> 2) + hrow * 8;
                if (grow < M) {
                    float o0 = acc[mt][nt][hrow * 2 + 0] + b0;
                    float o1 = acc[mt][nt][hrow * 2 + 1] + b1;
                    if (RELU) { o0 = fmaxf(o0, 0.f); o1 = fmaxf(o1, 0.f); }
                    *(float2*)(C + (size_t)grow * 128 + gcol) = make_float2(o0, o1);
                }
            }
        }
    }
}

// ---------------- launch ----------------
extern "C" void kernel_launch(void* const* d_in, const int* in_sizes, int n_in,
                              void* d_out, int out_size) {
    const float* x     = (const float*)d_in[0];
    const int*   ei    = (const int*)d_in[1];
    const int*   ea    = (const int*)d_in[2];
    const float* ee1_0 = (const float*)d_in[3];
    const float* ee2_0 = (const float*)d_in[4];
    const float* W1_0  = (const float*)d_in[5];
    const float* b1_0  = (const float*)d_in[6];
    const float* W2_0  = (const float*)d_in[7];
    const float* b2_0  = (const float*)d_in[8];
    const float* ee1_1 = (const float*)d_in[9];
    const float* ee2_1 = (const float*)d_in[10];
    const float* W1_1  = (const float*)d_in[11];
    const float* b1_1  = (const float*)d_in[12];
    const float* W2_1  = (const float*)d_in[13];
    const float* b2_1  = (const float*)d_in[14];
    float* out = (float*)d_out;

    const int N = in_sizes[0] / DD;  // 50000
    const int E = in_sizes[1] / 2;   // 800000

    float *y0;
    __nv_bfloat16 *Ahi, *Alo, *Hhi, *Hlo, *Wt;
    int* cnt;
    uint32_t* payload;
    cudaGetSymbolAddress((void**)&y0, g_y0);
    cudaGetSymbolAddress((void**)&Ahi, g_Ahi);
    cudaGetSymbolAddress((void**)&Alo, g_Alo);
    cudaGetSymbolAddress((void**)&Hhi, g_Hhi);
    cudaGetSymbolAddress((void**)&Hlo, g_Hlo);
    cudaGetSymbolAddress((void**)&Wt, g_Wt);
    cudaGetSymbolAddress((void**)&cnt, g_cnt);
    cudaGetSymbolAddress((void**)&payload, g_payload);

    cudaFuncSetAttribute(gemm1_bfA, cudaFuncAttributeMaxDynamicSharedMemorySize, GEMM_SMEM);
    cudaFuncSetAttribute(gemm2_bfA<true>, cudaFuncAttributeMaxDynamicSharedMemorySize, GEMM_SMEM);
    cudaFuncSetAttribute(gemm2_bfA<false>, cudaFuncAttributeMaxDynamicSharedMemorySize, GEMM_SMEM);

    const int MT = (N + 63) / 64;    // 782
    dim3 g1grid(2, MT);
    dim3 g2grid(1, MT);
    const int ggrid = (N + 7) / 8;

    // ---- bucket-CSR build (edge structure shared by both layers) ----
    prep_kernel<<<512 + (NN + 255) / 256, 256>>>(W1_0, W2_0, W1_1, W2_1, Wt, cnt);
    fill_kernel<<<(E + 255) / 256, 256>>>(ei, ea, cnt, payload, E);

    // ============ layer 0 ============
    gather_kernel<<<ggrid, 256>>>(x, cnt, payload, ee1_0, ee2_0, Ahi, Alo, N);
    gemm1_bfA<<<g1grid, 256, GEMM_SMEM>>>(Ahi, Alo, Wt + 0 * 32768, Wt + 1 * 32768, b1_0, Hhi, Hlo, N);
    gemm2_bfA<true><<<g2grid, 256, GEMM_SMEM>>>(Hhi, Hlo, Wt + 2 * 32768, Wt + 3 * 32768, b2_0, y0, N);

    // ============ layer 1 ============
    gather_kernel<<<ggrid, 256>>>(y0, cnt, payload, ee1_1, ee2_1, Ahi, Alo, N);
    gemm1_bfA<<<g1grid, 256, GEMM_SMEM>>>(Ahi, Alo, Wt + 4 * 32768, Wt + 5 * 32768, b1_1, Hhi, Hlo, N);
    gemm2_bfA<false><<<g2grid, 256, GEMM_SMEM>>>(Hhi, Hlo, Wt + 6 * 32768, Wt + 7 * 32768, b2_1, out, N);
}

// round 8
// speedup vs baseline: 2.3958x; 1.0165x over previous
#include <cuda_runtime.h>
#include <cuda_bf16.h>
#include <cstdint>

#define NN 50000
#define EE 800000
#define DD 128
#define BUCKET 64
#define GRIDP 148
#define NT 1563              // ceil(50000/32)

// ---------------- scratch (static device globals) ----------------
__device__ float g_y0[(size_t)NN * DD];                   // 25.6 MB
__device__ __nv_bfloat16 g_Ahi[(size_t)NN * DD];
__device__ __nv_bfloat16 g_Alo[(size_t)NN * DD];
__device__ __nv_bfloat16 g_Hhi[(size_t)NN * 2 * DD];
__device__ __nv_bfloat16 g_Hlo[(size_t)NN * 2 * DD];
__device__ __nv_bfloat16 g_Wt[8][256 * 128];
__device__ int g_cnt[NN];
__device__ uint32_t g_payload[(size_t)NN * BUCKET];

// ---------------- PTX helpers (base ISA only) ----------------
__device__ __forceinline__ uint32_t smem_u32(const void* p) {
    uint32_t a;
    asm("{ .reg .u64 t; cvta.to.shared.u64 t, %1; cvt.u32.u64 %0, t; }" : "=r"(a) : "l"(p));
    return a;
}
__device__ __forceinline__ void cp_async16(uint32_t dst, const void* src, int srcbytes) {
    asm volatile("cp.async.cg.shared.global [%0], [%1], 16, %2;"
                 :: "r"(dst), "l"(src), "r"(srcbytes) : "memory");
}
__device__ __forceinline__ void cp_commit() { asm volatile("cp.async.commit_group;" ::: "memory"); }
__device__ __forceinline__ void cp_wait0()  { asm volatile("cp.async.wait_group 0;" ::: "memory"); }

__device__ __forceinline__ void ldsm_x4(uint32_t& r0, uint32_t& r1, uint32_t& r2, uint32_t& r3,
                                        uint32_t addr) {
    asm volatile("ldmatrix.sync.aligned.m8n8.x4.shared.b16 {%0,%1,%2,%3}, [%4];"
                 : "=r"(r0), "=r"(r1), "=r"(r2), "=r"(r3) : "r"(addr));
}
__device__ __forceinline__ void mma16816(float* d, const uint32_t* a, const uint32_t* b) {
    asm volatile(
        "mma.sync.aligned.m16n8k16.row.col.f32.bf16.bf16.f32 "
        "{%0,%1,%2,%3}, {%4,%5,%6,%7}, {%8,%9}, {%0,%1,%2,%3};"
        : "+f"(d[0]), "+f"(d[1]), "+f"(d[2]), "+f"(d[3])
        : "r"(a[0]), "r"(a[1]), "r"(a[2]), "r"(a[3]), "r"(b[0]), "r"(b[1]));
}

// ---------------- prep: weight transposes + zero cnt ----------------
__global__ void __launch_bounds__(256)
prep_kernel(const float* __restrict__ W10, const float* __restrict__ W20,
            const float* __restrict__ W11, const float* __restrict__ W21,
            __nv_bfloat16* __restrict__ wt, int* __restrict__ cnt) {
    int b = blockIdx.x;
    if (b >= 512) {
        int i = (b - 512) * 256 + threadIdx.x;
        if (i < NN) cnt[i] = 0;
        return;
    }
    int which = b >> 7;
    int i = ((b & 127) << 8) + threadIdx.x;
    const float* W;
    int K, N;
    if (which == 0)      { W = W10; K = 128; N = 256; }
    else if (which == 1) { W = W20; K = 256; N = 128; }
    else if (which == 2) { W = W11; K = 128; N = 256; }
    else                 { W = W21; K = 256; N = 128; }
    int k = i / N, n = i % N;
    float a = W[i];
    __nv_bfloat16 h = __float2bfloat16_rn(a);
    __nv_bfloat16 l = __float2bfloat16_rn(a - __bfloat162float(h));
    __nv_bfloat16* thi = wt + (size_t)(2 * which) * 32768;
    __nv_bfloat16* tlo = thi + 32768;
    thi[n * K + k] = h;
    tlo[n * K + k] = l;
}

// ---------------- bucket fill ----------------
__global__ void __launch_bounds__(256)
fill_kernel(const int* __restrict__ ei, const int* __restrict__ ea,
            int* __restrict__ cnt, uint32_t* __restrict__ payload, int E) {
    int e = blockIdx.x * 256 + threadIdx.x;
    if (e >= E) return;
    int src = ei[e];
    int dst = ei[E + e];
    int a0 = ea[2 * e];
    int a1 = ea[2 * e + 1];
    int pos = atomicAdd(&cnt[dst], 1);
    payload[((size_t)dst << 6) + pos] = (uint32_t)src | ((uint32_t)(a0 * 3 + a1) << 16);
}

// ---------------- gather -> bf16 hi/lo ----------------
__global__ void __launch_bounds__(256)
gather_kernel(const float* __restrict__ x,
              const int* __restrict__ cnt, const uint32_t* __restrict__ payload,
              const float* __restrict__ ee1, const float* __restrict__ ee2,
              __nv_bfloat16* __restrict__ Ahi, __nv_bfloat16* __restrict__ Alo,
              int N) {
    __shared__ float combo[18 * 128];
    const int tid = threadIdx.x;
#pragma unroll
    for (int k = 0; k < 9; k++) {
        int idx = tid + k * 256;
        int c = idx >> 7, d = idx & 127;
        combo[idx] = ee1[(c / 3) * 128 + d] + ee2[(c % 3) * 128 + d];
    }
    __syncthreads();

    const int lane = tid & 31;
    const int n = blockIdx.x * 8 + (tid >> 5);
    if (n >= N) return;
    const int d4 = lane * 4;

    const uint32_t* pl = payload + ((size_t)n << 6);
    int deg = cnt[n];
    float4 acc = make_float4(0.f, 0.f, 0.f, 0.f);
    int i = 0;
    for (; i + 3 < deg; i += 4) {
        uint32_t p0 = pl[i], p1 = pl[i + 1], p2 = pl[i + 2], p3 = pl[i + 3];
        float4 x0 = *(const float4*)(x + (size_t)(p0 & 0xFFFF) * 128 + d4);
        float4 x1 = *(const float4*)(x + (size_t)(p1 & 0xFFFF) * 128 + d4);
        float4 x2 = *(const float4*)(x + (size_t)(p2 & 0xFFFF) * 128 + d4);
        float4 x3 = *(const float4*)(x + (size_t)(p3 & 0xFFFF) * 128 + d4);
        float4 c0 = *(const float4*)(combo + (p0 >> 16) * 128 + d4);
        float4 c1 = *(const float4*)(combo + (p1 >> 16) * 128 + d4);
        float4 c2 = *(const float4*)(combo + (p2 >> 16) * 128 + d4);
        float4 c3 = *(const float4*)(combo + (p3 >> 16) * 128 + d4);
        acc.x += (x0.x + c0.x) + (x1.x + c1.x) + (x2.x + c2.x) + (x3.x + c3.x);
        acc.y += (x0.y + c0.y) + (x1.y + c1.y) + (x2.y + c2.y) + (x3.y + c3.y);
        acc.z += (x0.z + c0.z) + (x1.z + c1.z) + (x2.z + c2.z) + (x3.z + c3.z);
        acc.w += (x0.w + c0.w) + (x1.w + c1.w) + (x2.w + c2.w) + (x3.w + c3.w);
    }
    for (; i < deg; i++) {
        uint32_t p0 = pl[i];
        float4 x0 = *(const float4*)(x + (size_t)(p0 & 0xFFFF) * 128 + d4);
        float4 c0 = *(const float4*)(combo + (p0 >> 16) * 128 + d4);
        acc.x += x0.x + c0.x;
        acc.y += x0.y + c0.y;
        acc.z += x0.z + c0.z;
        acc.w += x0.w + c0.w;
    }

    __nv_bfloat16 h0 = __float2bfloat16_rn(acc.x), h1 = __float2bfloat16_rn(acc.y);
    __nv_bfloat16 h2 = __float2bfloat16_rn(acc.z), h3 = __float2bfloat16_rn(acc.w);
    __nv_bfloat16 l0 = __float2bfloat16_rn(acc.x - __bfloat162float(h0));
    __nv_bfloat16 l1 = __float2bfloat16_rn(acc.y - __bfloat162float(h1));
    __nv_bfloat16 l2 = __float2bfloat16_rn(acc.z - __bfloat162float(h2));
    __nv_bfloat16 l3 = __float2bfloat16_rn(acc.w - __bfloat162float(h3));
    __nv_bfloat162 hp0(h0, h1), hp1(h2, h3), lp0(l0, l1), lp1(l2, l3);
    size_t o = (size_t)n * 128 + d4;
    *(uint2*)(Ahi + o) = make_uint2(*(uint32_t*)&hp0, *(uint32_t*)&hp1);
    *(uint2*)(Alo + o) = make_uint2(*(uint32_t*)&lp0, *(uint32_t*)&lp1);
}

// =============== persistent GEMM 1: H = relu(A @ Wt1^T + b1) ================
// A [M,128] bf16 hi/lo. Wt1 [256,128] hi/lo RESIDENT in smem. Tile 32x256.
// 512 threads = 16 warps: warp (wid&1)->M half, (wid>>1)->32-col group.
#define SROWB 272
#define G1_B (256 * SROWB)            // 69632 per matrix
#define G1_AB (32 * SROWB)            // 8704 per matrix
#define G1_ABUF (2 * G1_AB)           // 17408 per buffer (hi+lo)
#define G1_SMEM (2 * G1_B + 2 * G1_ABUF)   // 174080

__global__ void __launch_bounds__(512, 1)
gemm1p(const __nv_bfloat16* __restrict__ Ahi, const __nv_bfloat16* __restrict__ Alo,
       const __nv_bfloat16* __restrict__ Bhi, const __nv_bfloat16* __restrict__ Blo,
       const float* __restrict__ bias,
       __nv_bfloat16* __restrict__ Hhi, __nv_bfloat16* __restrict__ Hlo, int M) {
    extern __shared__ char smem[];
    const uint32_t sb = smem_u32(smem);
    const uint32_t sBhi = sb;
    const uint32_t sBlo = sb + G1_B;
    const uint32_t sA0  = sb + 2 * G1_B;   // buf: [Ahi | Alo]

    const int tid  = threadIdx.x;
    const int lane = tid & 31;
    const int wid  = tid >> 5;
    const int wm   = (wid & 1) * 16;
    const int wn   = (wid >> 1) * 32;

    // ---- load resident B: 256 rows x 256B, hi+lo ----
#pragma unroll
    for (int i = 0; i < 8; i++) {
        int id = tid + i * 512;
        int row = id >> 4, off = (id & 15) * 16;
        uint32_t sdst = (uint32_t)(row * SROWB + off);
        cp_async16(sBhi + sdst, (const char*)(Bhi + (size_t)row * 128) + off, 16);
        cp_async16(sBlo + sdst, (const char*)(Blo + (size_t)row * 128) + off, 16);
    }

    // ---- issue first A tile ----
    int t = blockIdx.x;
    const int arow_ld = tid >> 4;
    const int aoff_ld = (tid & 15) * 16;
    if (t < NT) {
        int grow = t * 32 + arow_ld;
        int asz = grow < M ? 16 : 0;
        uint32_t sdst = (uint32_t)(arow_ld * SROWB + aoff_ld);
        cp_async16(sA0 + sdst, (const char*)(Ahi + (size_t)grow * 128) + aoff_ld, asz);
        cp_async16(sA0 + G1_AB + sdst, (const char*)(Alo + (size_t)grow * 128) + aoff_ld, asz);
    }
    cp_commit();

    int buf = 0;
    for (; t < NT; t += GRIDP) {
        cp_wait0();
        __syncthreads();

        // issue next tile into other buffer
        int tn = t + GRIDP;
        if (tn < NT) {
            uint32_t base = sA0 + (buf ^ 1) * G1_ABUF;
            int grow = tn * 32 + arow_ld;
            int asz = grow < M ? 16 : 0;
            uint32_t sdst = (uint32_t)(arow_ld * SROWB + aoff_ld);
            cp_async16(base + sdst, (const char*)(Ahi + (size_t)grow * 128) + aoff_ld, asz);
            cp_async16(base + G1_AB + sdst, (const char*)(Alo + (size_t)grow * 128) + aoff_ld, asz);
        }
        cp_commit();

        // ---- compute tile from buf ----
        const uint32_t cAhi = sA0 + buf * G1_ABUF;
        const uint32_t cAlo = cAhi + G1_AB;
        float acc[4][4];
#pragma unroll
        for (int j = 0; j < 4; j++)
#pragma unroll
            for (int k = 0; k < 4; k++) acc[j][k] = 0.f;

#pragma unroll
        for (int kk = 0; kk < 8; kk++) {
            const uint32_t kb = (uint32_t)(kk * 32);
            uint32_t ah[4], al[4];
            {
                uint32_t arow = (uint32_t)(wm + (lane & 15));
                uint32_t aoff = arow * SROWB + kb + ((lane >> 4) << 4);
                ldsm_x4(ah[0], ah[1], ah[2], ah[3], cAhi + aoff);
                ldsm_x4(al[0], al[1], al[2], al[3], cAlo + aoff);
            }
            uint32_t bh[4][2], bl[4][2];
#pragma unroll
            for (int np = 0; np < 2; np++) {
                int g = lane >> 3, r = lane & 7;
                uint32_t browi = (uint32_t)(wn + np * 16 + ((g & 2) ? 8 : 0) + r);
                uint32_t boff = browi * SROWB + kb + ((g & 1) << 4);
                uint32_t r0, r1, r2, r3;
                ldsm_x4(r0, r1, r2, r3, sBhi + boff);
                bh[np * 2][0] = r0; bh[np * 2][1] = r1;
                bh[np * 2 + 1][0] = r2; bh[np * 2 + 1][1] = r3;
                ldsm_x4(r0, r1, r2, r3, sBlo + boff);
                bl[np * 2][0] = r0; bl[np * 2][1] = r1;
                bl[np * 2 + 1][0] = r2; bl[np * 2 + 1][1] = r3;
            }
#pragma unroll
            for (int nt = 0; nt < 4; nt++) {
                mma16816(acc[nt], ah, bh[nt]);
                mma16816(acc[nt], ah, bl[nt]);
                mma16816(acc[nt], al, bh[nt]);
            }
        }

        // ---- epilogue: bias+relu, hi/lo split ----
        const int brow = t * 32;
#pragma unroll
        for (int nt = 0; nt < 4; nt++) {
            int gcol = wn + nt * 8 + (lane & 3) * 2;
            float b0 = bias[gcol], b1 = bias[gcol + 1];
#pragma unroll
            for (int hrow = 0; hrow < 2; hrow++) {
                int grow = brow + wm + (lane >> 2) + hrow * 8;
                if (grow < M) {
                    float o0 = fmaxf(acc[nt][hrow * 2 + 0] + b0, 0.f);
                    float o1 = fmaxf(acc[nt][hrow * 2 + 1] + b1, 0.f);
                    __nv_bfloat16 h0 = __float2bfloat16_rn(o0);
                    __nv_bfloat16 h1 = __float2bfloat16_rn(o1);
                    __nv_bfloat16 l0 = __float2bfloat16_rn(o0 - __bfloat162float(h0));
                    __nv_bfloat16 l1 = __float2bfloat16_rn(o1 - __bfloat162float(h1));
                    __nv_bfloat162 hp(h0, h1), lp(l0, l1);
                    size_t o = (size_t)grow * 256 + gcol;
                    *(__nv_bfloat162*)(Hhi + o) = hp;
                    *(__nv_bfloat162*)(Hlo + o) = lp;
                }
            }
        }
        buf ^= 1;
    }
}

// =============== persistent GEMM 2: C = act(H @ Wt2^T + b2) =================
// A=H [M,256] bf16 hi/lo. Wt2 [128,256] hi/lo RESIDENT. Tile 32x128, K=256.
#define SROW2 528
#define G2_B (128 * SROW2)            // 67584 per matrix
#define G2_AB (32 * SROW2)            // 16896 per matrix
#define G2_ABUF (2 * G2_AB)           // 33792 per buffer
#define G2_SMEM (2 * G2_B + 2 * G2_ABUF)   // 202752

template <bool RELU>
__global__ void __launch_bounds__(512, 1)
gemm2p(const __nv_bfloat16* __restrict__ Ahi, const __nv_bfloat16* __restrict__ Alo,
       const __nv_bfloat16* __restrict__ Bhi, const __nv_bfloat16* __restrict__ Blo,
       const float* __restrict__ bias, float* __restrict__ C, int M) {
    extern __shared__ char smem[];
    const uint32_t sb = smem_u32(smem);
    const uint32_t sBhi = sb;
    const uint32_t sBlo = sb + G2_B;
    const uint32_t sA0  = sb + 2 * G2_B;

    const int tid  = threadIdx.x;
    const int lane = tid & 31;
    const int wid  = tid >> 5;
    const int wm   = (wid & 1) * 16;
    const int wn   = (wid >> 1) * 16;

    // ---- load resident B: 128 rows x 512B, hi+lo ----
#pragma unroll
    for (int i = 0; i < 8; i++) {
        int id = tid + i * 512;
        int row = id >> 5, off = (id & 31) * 16;
        uint32_t sdst = (uint32_t)(row * SROW2 + off);
        cp_async16(sBhi + sdst, (const char*)(Bhi + (size_t)row * 256) + off, 16);
        cp_async16(sBlo + sdst, (const char*)(Blo + (size_t)row * 256) + off, 16);
    }

    int t = blockIdx.x;
    if (t < NT) {
#pragma unroll
        for (int i = 0; i < 2; i++) {
            int id = tid + i * 512;
            int row = id >> 5, off = (id & 31) * 16;
            int grow = t * 32 + row;
            int asz = grow < M ? 16 : 0;
            uint32_t sdst = (uint32_t)(row * SROW2 + off);
            cp_async16(sA0 + sdst, (const char*)(Ahi + (size_t)grow * 256) + off, asz);
            cp_async16(sA0 + G2_AB + sdst, (const char*)(Alo + (size_t)grow * 256) + off, asz);
        }
    }
    cp_commit();

    int buf = 0;
    for (; t < NT; t += GRIDP) {
        cp_wait0();
        __syncthreads();

        int tn = t + GRIDP;
        if (tn < NT) {
            uint32_t base = sA0 + (buf ^ 1) * G2_ABUF;
#pragma unroll
            for (int i = 0; i < 2; i++) {
                int id = tid + i * 512;
                int row = id >> 5, off = (id & 31) * 16;
                int grow = tn * 32 + row;
                int asz = grow < M ? 16 : 0;
                uint32_t sdst = (uint32_t)(row * SROW2 + off);
                cp_async16(base + sdst, (const char*)(Ahi + (size_t)grow * 256) + off, asz);
                cp_async16(base + G2_AB + sdst, (const char*)(Alo + (size_t)grow * 256) + off, asz);
            }
        }
        cp_commit();

        const uint32_t cAhi = sA0 + buf * G2_ABUF;
        const uint32_t cAlo = cAhi + G2_AB;
        float acc[2][4];
#pragma unroll
        for (int j = 0; j < 2; j++)
#pragma unroll
            for (int k = 0; k < 4; k++) acc[j][k] = 0.f;

#pragma unroll
        for (int kk = 0; kk < 16; kk++) {
            const uint32_t kb = (uint32_t)(kk * 32);
            uint32_t ah[4], al[4];
            {
                uint32_t arow = (uint32_t)(wm + (lane & 15));
                uint32_t aoff = arow * SROW2 + kb + ((lane >> 4) << 4);
                ldsm_x4(ah[0], ah[1], ah[2], ah[3], cAhi + aoff);
                ldsm_x4(al[0], al[1], al[2], al[3], cAlo + aoff);
            }
            uint32_t bh[2][2], bl[2][2];
            {
                int g = lane >> 3, r = lane & 7;
                uint32_t browi = (uint32_t)(wn + ((g & 2) ? 8 : 0) + r);
                uint32_t boff = browi * SROW2 + kb + ((g & 1) << 4);
                uint32_t r0, r1, r2, r3;
                ldsm_x4(r0, r1, r2, r3, sBhi + boff);
                bh[0][0] = r0; bh[0][1] = r1;
                bh[1][0] = r2; bh[1][1] = r3;
                ldsm_x4(r0, r1, r2, r3, sBlo + boff);
                bl[0][0] = r0; bl[0][1] = r1;
                bl[1][0] = r2; bl[1][1] = r3;
            }
#pragma unroll
            for (int nt = 0; nt < 2; nt++) {
                mma16816(acc[nt], ah, bh[nt]);
                mma16816(acc[nt], ah, bl[nt]);
                mma16816(acc[nt], al, bh[nt]);
            }
        }

        const int brow = t * 32;
#pragma unroll
        for (int nt = 0; nt < 2; nt++) {
            int gcol = wn + nt * 8 + (lane & 3) * 2;
            float b0 = bias[gcol], b1 = bias[gcol + 1];
#pragma unroll
            for (int hrow = 0; hrow < 2; hrow++) {
                int grow = brow + wm + (lane >> 2) + hrow * 8;
                if (grow < M) {
                    float o0 = acc[nt][hrow * 2 + 0] + b0;
                    float o1 = acc[nt][hrow * 2 + 1] + b1;
                    if (RELU) { o0 = fmaxf(o0, 0.f); o1 = fmaxf(o1, 0.f); }
                    *(float2*)(C + (size_t)grow * 128 + gcol) = make_float2(o0, o1);
                }
            }
        }
        buf ^= 1;
    }
}

// ---------------- launch ----------------
extern "C" void kernel_launch(void* const* d_in, const int* in_sizes, int n_in,
                              void* d_out, int out_size) {
    const float* x     = (const float*)d_in[0];
    const int*   ei    = (const int*)d_in[1];
    const int*   ea    = (const int*)d_in[2];
    const float* ee1_0 = (const float*)d_in[3];
    const float* ee2_0 = (const float*)d_in[4];
    const float* W1_0  = (const float*)d_in[5];
    const float* b1_0  = (const float*)d_in[6];
    const float* W2_0  = (const float*)d_in[7];
    const float* b2_0  = (const float*)d_in[8];
    const float* ee1_1 = (const float*)d_in[9];
    const float* ee2_1 = (const float*)d_in[10];
    const float* W1_1  = (const float*)d_in[11];
    const float* b1_1  = (const float*)d_in[12];
    const float* W2_1  = (const float*)d_in[13];
    const float* b2_1  = (const float*)d_in[14];
    float* out = (float*)d_out;

    const int N = in_sizes[0] / DD;
    const int E = in_sizes[1] / 2;

    float *y0;
    __nv_bfloat16 *Ahi, *Alo, *Hhi, *Hlo, *Wt;
    int* cnt;
    uint32_t* payload;
    cudaGetSymbolAddress((void**)&y0, g_y0);
    cudaGetSymbolAddress((void**)&Ahi, g_Ahi);
    cudaGetSymbolAddress((void**)&Alo, g_Alo);
    cudaGetSymbolAddress((void**)&Hhi, g_Hhi);
    cudaGetSymbolAddress((void**)&Hlo, g_Hlo);
    cudaGetSymbolAddress((void**)&Wt, g_Wt);
    cudaGetSymbolAddress((void**)&cnt, g_cnt);
    cudaGetSymbolAddress((void**)&payload, g_payload);

    cudaFuncSetAttribute(gemm1p, cudaFuncAttributeMaxDynamicSharedMemorySize, G1_SMEM);
    cudaFuncSetAttribute(gemm2p<true>, cudaFuncAttributeMaxDynamicSharedMemorySize, G2_SMEM);
    cudaFuncSetAttribute(gemm2p<false>, cudaFuncAttributeMaxDynamicSharedMemorySize, G2_SMEM);

    const int ggrid = (N + 7) / 8;

    prep_kernel<<<512 + (NN + 255) / 256, 256>>>(W1_0, W2_0, W1_1, W2_1, Wt, cnt);
    fill_kernel<<<(E + 255) / 256, 256>>>(ei, ea, cnt, payload, E);

    // ============ layer 0 ============
    gather_kernel<<<ggrid, 256>>>(x, cnt, payload, ee1_0, ee2_0, Ahi, Alo, N);
    gemm1p<<<GRIDP, 512, G1_SMEM>>>(Ahi, Alo, Wt + 0 * 32768, Wt + 1 * 32768, b1_0, Hhi, Hlo, N);
    gemm2p<true><<<GRIDP, 512, G2_SMEM>>>(Hhi, Hlo, Wt + 2 * 32768, Wt + 3 * 32768, b2_0, y0, N);

    // ============ layer 1 ============
    gather_kernel<<<ggrid, 256>>>(y0, cnt, payload, ee1_1, ee2_1, Ahi, Alo, N);
    gemm1p<<<GRIDP, 512, G1_SMEM>>>(Ahi, Alo, Wt + 4 * 32768, Wt + 5 * 32768, b1_1, Hhi, Hlo, N);
    gemm2p<false><<<GRIDP, 512, G2_SMEM>>>(Hhi, Hlo, Wt + 6 * 32768, Wt + 7 * 32768, b2_1, out, N);
}